// round 4
// baseline (speedup 1.0000x reference)
#include <cuda_runtime.h>
#include <cuda_fp16.h>
#include <cstdint>

// Problem constants
#define NTOK 65536
#define IN   512
#define OUT  512
#define NE   8
#define NS   64

// GEMM tiling
#define TM 128
#define TN 256
#define KC 32
#define NCHUNK (IN / KC)          // 16
#define MAXT 576                  // sum ceil(c/128) <= 512+64
#define LDSS 80                   // smem row stride (bytes): conflict-free ldmatrix

#define A_PLANE (TM * LDSS)       // 10240
#define B_PLANE (TN * LDSS)       // 20480
#define OFF_B   (2 * A_PLANE)
#define STAGE_BYTES (2 * A_PLANE + B_PLANE)   // 40960
#define STAGES 4
#define OFF_PERM (STAGES * STAGE_BYTES)       // 163840
#define GSMEM (OFF_PERM + 512)                // 164352

// ---------------- device scratch (static; no allocation) ---------------------
__device__ __half g_xh[(size_t)NTOK * IN];
__device__ __half g_xl[(size_t)NTOK * IN];
__device__ __half g_Mh[(size_t)NS * OUT * IN];
__device__ int g_counts[NS];
__device__ int g_cursor[NS];
__device__ int g_perm[NTOK];
__device__ int g_tile_sys[MAXT];
__device__ int g_tile_start[MAXT];
__device__ int g_tile_rows[MAXT];

// ---------------- helpers -----------------------------------------------------
__device__ __forceinline__ uint32_t smem_u32(const void* p) {
    uint32_t a;
    asm("{ .reg .u64 t; cvta.to.shared.u64 t, %1; cvt.u32.u64 %0, t; }"
        : "=r"(a) : "l"(p));
    return a;
}
__device__ __forceinline__ void cpa16(uint32_t dst, const void* src) {
    asm volatile("cp.async.cg.shared.global [%0], [%1], 16;"
                 :: "r"(dst), "l"(src) : "memory");
}
__device__ __forceinline__ void ldsm4(uint32_t* r, uint32_t addr) {
    asm volatile("ldmatrix.sync.aligned.m8n8.x4.shared.b16 {%0,%1,%2,%3}, [%4];"
                 : "=r"(r[0]), "=r"(r[1]), "=r"(r[2]), "=r"(r[3]) : "r"(addr));
}
__device__ __forceinline__ void mma16816(float* c, const uint32_t* a,
                                         uint32_t b0, uint32_t b1) {
    asm volatile(
        "mma.sync.aligned.m16n8k16.row.col.f32.f16.f16.f32 "
        "{%0,%1,%2,%3}, {%4,%5,%6,%7}, {%8,%9}, {%0,%1,%2,%3};"
        : "+f"(c[0]), "+f"(c[1]), "+f"(c[2]), "+f"(c[3])
        : "r"(a[0]), "r"(a[1]), "r"(a[2]), "r"(a[3]), "r"(b0), "r"(b1));
}
// fp32x4 -> fp16 hi/lo planes (each uint2 = 4 halves)
__device__ __forceinline__ void split4h(float4 v, uint2& hi, uint2& lo) {
    __half2 h01 = __floats2half2_rn(v.x, v.y);
    __half2 h23 = __floats2half2_rn(v.z, v.w);
    float2 f01 = __half22float2(h01);
    float2 f23 = __half22float2(h23);
    __half2 l01 = __floats2half2_rn(v.x - f01.x, v.y - f01.y);
    __half2 l23 = __floats2half2_rn(v.z - f23.x, v.w - f23.y);
    hi = make_uint2(*(uint32_t*)&h01, *(uint32_t*)&h23);
    lo = make_uint2(*(uint32_t*)&l01, *(uint32_t*)&l23);
}
__device__ __forceinline__ uint2 round4h(float4 v) {
    __half2 h01 = __floats2half2_rn(v.x, v.y);
    __half2 h23 = __floats2half2_rn(v.z, v.w);
    return make_uint2(*(uint32_t*)&h01, *(uint32_t*)&h23);
}

// ---------------- kernel 0: reset ---------------------------------------------
__global__ void init_kernel() {
    if (threadIdx.x < NS) g_counts[threadIdx.x] = 0;
}

// ---------------- kernel 1: histogram (block-aggregated) ----------------------
__global__ void hist_kernel(const int* __restrict__ bi) {
    __shared__ int h[NS];
    int tid = threadIdx.x;
    if (tid < NS) h[tid] = 0;
    __syncthreads();
    int n = blockIdx.x * blockDim.x + tid;
    atomicAdd(&h[bi[n]], 1);
    __syncthreads();
    if (tid < NS && h[tid] != 0) atomicAdd(&g_counts[tid], h[tid]);
}

// ---------------- kernel 2: scan + tile table ---------------------------------
__global__ void plan_kernel() {
    __shared__ int cnt[NS], offs[NS], tbase[NS];
    int tid = threadIdx.x;
    if (tid < NS) cnt[tid] = g_counts[tid];
    __syncthreads();
    if (tid == 0) {
        int off = 0, tb = 0;
        for (int s = 0; s < NS; ++s) {
            offs[s] = off; tbase[s] = tb;
            off += cnt[s];
            tb  += (cnt[s] + TM - 1) / TM;
        }
    }
    __syncthreads();
    for (int i = tid; i < MAXT; i += blockDim.x) g_tile_rows[i] = 0;
    __syncthreads();
    if (tid < NS) {
        int s = tid, c = cnt[s], nt = (c + TM - 1) / TM;
        int tb = tbase[s], off = offs[s];
        g_cursor[s] = off;
        for (int k = 0; k < nt; ++k) {
            g_tile_sys[tb + k]   = s;
            g_tile_start[tb + k] = off + k * TM;
            int rem = c - k * TM;
            g_tile_rows[tb + k]  = rem < TM ? rem : TM;
        }
    }
}

// ---------------- kernel 3: scatter (block-aggregated) ------------------------
__global__ void scatter_kernel(const int* __restrict__ bi) {
    __shared__ int lc[NS], lbase[NS];
    int tid = threadIdx.x;
    if (tid < NS) lc[tid] = 0;
    __syncthreads();
    int n = blockIdx.x * blockDim.x + tid;
    int s = bi[n];
    int r = atomicAdd(&lc[s], 1);
    __syncthreads();
    if (tid < NS && lc[tid] > 0) lbase[tid] = atomicAdd(&g_cursor[tid], lc[tid]);
    __syncthreads();
    g_perm[lbase[s] + r] = n;
}

// ---------------- kernel 4: gather + split x into fp16 hi/lo planes -----------
__global__ __launch_bounds__(256) void prep_x(const float* __restrict__ x) {
    int idx = blockIdx.x * blockDim.x + threadIdx.x;   // over NTOK * 128
    int row = idx >> 7;
    int q   = idx & 127;
    int tok = g_perm[row];
    float4 v = ((const float4*)(x + (size_t)tok * IN))[q];
    uint2 hi, lo;
    split4h(v, hi, lo);
    ((uint2*)(g_xh + (size_t)row * IN))[q] = hi;
    ((uint2*)(g_xl + (size_t)row * IN))[q] = lo;
}

// ---------------- kernel 5: mix weights -> single fp16 plane ------------------
__global__ __launch_bounds__(256) void mix_kernel(const float* __restrict__ W,
                                                  const float* __restrict__ coeff) {
    __shared__ float sc[NS * NE];
    int tid = threadIdx.x;
    for (int i = tid; i < NS * NE; i += blockDim.x) sc[i] = coeff[i];
    __syncthreads();

    int idx = blockIdx.x * blockDim.x + tid;   // over OUT*IN/4
    int o  = idx >> 7;
    int q  = idx & 127;
    int i4 = q * 4;

    float4 w[NE];
#pragma unroll
    for (int e = 0; e < NE; ++e)
        w[e] = *(const float4*)(W + (size_t)e * OUT * IN + o * IN + i4);

#pragma unroll 4
    for (int s = 0; s < NS; ++s) {
        float4 acc = make_float4(0.f, 0.f, 0.f, 0.f);
#pragma unroll
        for (int e = 0; e < NE; ++e) {
            float c = sc[s * NE + e];
            acc.x = fmaf(c, w[e].x, acc.x);
            acc.y = fmaf(c, w[e].y, acc.y);
            acc.z = fmaf(c, w[e].z, acc.z);
            acc.w = fmaf(c, w[e].w, acc.w);
        }
        ((uint2*)(g_Mh + (size_t)(s * OUT + o) * IN))[q] = round4h(acc);
    }
}

// ---------------- kernel 6: grouped GEMM, fp16 2-pass (AhBh + AlBh) -----------
// CTA: 128 tokens x 256 outputs; 8 warps (2x4), warp tile 64x64.
// K=512 in 16 chunks of 32; 4-stage cp.async pipeline.
__global__ __launch_bounds__(256, 1) void gemm_kernel(const float* __restrict__ bias,
                                                      float* __restrict__ out) {
    int bt = blockIdx.x;
    int rows = g_tile_rows[bt];
    if (rows == 0) return;
    int sys       = g_tile_sys[bt];
    int row_start = g_tile_start[bt];
    int col0      = blockIdx.y * TN;

    extern __shared__ __align__(16) char smem[];
    uint32_t sm = smem_u32(smem);
    int tid = threadIdx.x, lane = tid & 31, wid = tid >> 5;
    int wm = wid >> 2, wn = wid & 3;

    int* sperm = (int*)(smem + OFF_PERM);
    if (tid < TM) {
        int rsi = row_start + tid;
        if (rsi > NTOK - 1) rsi = NTOK - 1;
        sperm[tid] = g_perm[rsi];
    }

    int arow = tid >> 2;
    int ac   = tid & 3;
    size_t sysbase = (size_t)sys * OUT * IN;

    auto load_chunk = [&](int stage, int k0) {
        uint32_t sb = sm + stage * STAGE_BYTES;
#pragma unroll
        for (int h = 0; h < 2; ++h) {
            int row = arow + h * 64;
            int srcrow = row_start + row;
            if (srcrow > NTOK - 1) srcrow = NTOK - 1;
            size_t goff = (size_t)srcrow * IN + k0 + ac * 8;
            cpa16(sb + 0 * A_PLANE + row * LDSS + ac * 16, g_xh + goff);
            cpa16(sb + 1 * A_PLANE + row * LDSS + ac * 16, g_xl + goff);
        }
#pragma unroll
        for (int h = 0; h < 4; ++h) {
            int row = arow + h * 64;
            size_t goff = sysbase + (size_t)(col0 + row) * IN + k0 + ac * 8;
            cpa16(sb + OFF_B + row * LDSS + ac * 16, g_Mh + goff);
        }
        asm volatile("cp.async.commit_group;" ::: "memory");
    };

    float acc[4][8][4];
#pragma unroll
    for (int mf = 0; mf < 4; ++mf)
#pragma unroll
        for (int nf = 0; nf < 8; ++nf)
#pragma unroll
            for (int r = 0; r < 4; ++r) acc[mf][nf][r] = 0.f;

    load_chunk(0, 0);
    load_chunk(1, KC);
    load_chunk(2, 2 * KC);

    int lrow = lane & 15, kseg = lane >> 4;
    uint32_t a_base = (uint32_t)((wm * 64 + lrow) * LDSS + kseg * 16);
    uint32_t b_base = (uint32_t)(OFF_B + (wn * 64 + lrow) * LDSS + kseg * 16);

#pragma unroll 1
    for (int c = 0; c < NCHUNK; ++c) {
        int rem = NCHUNK - 1 - c;
        if (rem >= 2)      asm volatile("cp.async.wait_group 2;" ::: "memory");
        else if (rem == 1) asm volatile("cp.async.wait_group 1;" ::: "memory");
        else               asm volatile("cp.async.wait_group 0;" ::: "memory");
        __syncthreads();
        uint32_t sb = sm + (c % STAGES) * STAGE_BYTES;

#pragma unroll
        for (int kk = 0; kk < 2; ++kk) {
            uint32_t ah[4][4], al[4][4], bb[4][4];
#pragma unroll
            for (int mf = 0; mf < 4; ++mf) {
                uint32_t ad = sb + a_base + mf * 16 * LDSS + kk * 32;
                ldsm4(ah[mf], ad);
                ldsm4(al[mf], ad + A_PLANE);
            }
#pragma unroll
            for (int bf = 0; bf < 4; ++bf)
                ldsm4(bb[bf], sb + b_base + bf * 16 * LDSS + kk * 32);
            // pass 1: Ah * B
#pragma unroll
            for (int mf = 0; mf < 4; ++mf)
#pragma unroll
                for (int nf = 0; nf < 8; ++nf)
                    mma16816(acc[mf][nf], ah[mf],
                             bb[nf >> 1][nf & 1], bb[nf >> 1][(nf & 1) + 2]);
            // pass 2: Al * B
#pragma unroll
            for (int mf = 0; mf < 4; ++mf)
#pragma unroll
                for (int nf = 0; nf < 8; ++nf)
                    mma16816(acc[mf][nf], al[mf],
                             bb[nf >> 1][nf & 1], bb[nf >> 1][(nf & 1) + 2]);
        }
        if (c + 3 < NCHUNK) load_chunk((c + 3) % STAGES, (c + 3) * KC);
    }

    // ---------------- epilogue: bias + scatter -------------------------------
    int g  = lane >> 2;
    int tc = (lane & 3) * 2;
    const float* bptr = bias + col0 + wn * 64 + tc;
    float2 bv[8];
#pragma unroll
    for (int nf = 0; nf < 8; ++nf)
        bv[nf] = make_float2(bptr[nf * 8], bptr[nf * 8 + 1]);

#pragma unroll
    for (int mf = 0; mf < 4; ++mf) {
#pragma unroll
        for (int rh = 0; rh < 2; ++rh) {
            int lr = wm * 64 + mf * 16 + rh * 8 + g;
            if (lr < rows) {
                float* orow = out + (size_t)sperm[lr] * OUT + col0 + wn * 64 + tc;
#pragma unroll
                for (int nf = 0; nf < 8; ++nf) {
                    float2 v = make_float2(acc[mf][nf][rh * 2]     + bv[nf].x,
                                           acc[mf][nf][rh * 2 + 1] + bv[nf].y);
                    *(float2*)(orow + nf * 8) = v;
                }
            }
        }
    }
}

// ---------------- launch -----------------------------------------------------
extern "C" void kernel_launch(void* const* d_in, const int* in_sizes, int n_in,
                              void* d_out, int out_size) {
    const float* x     = (const float*)d_in[0];
    const float* coeff = (const float*)d_in[1];
    const int*   bidx  = (const int*)d_in[2];
    const float* W     = (const float*)d_in[3];
    const float* bias  = (const float*)d_in[4];
    float*       out   = (float*)d_out;

    cudaFuncSetAttribute(gemm_kernel, cudaFuncAttributeMaxDynamicSharedMemorySize,
                         GSMEM);

    init_kernel<<<1, 64>>>();
    hist_kernel<<<NTOK / 1024, 1024>>>(bidx);
    plan_kernel<<<1, 256>>>();
    scatter_kernel<<<NTOK / 1024, 1024>>>(bidx);
    prep_x<<<NTOK * (IN / 4) / 256, 256>>>(x);
    mix_kernel<<<(OUT * IN / 4) / 256, 256>>>(W, coeff);
    gemm_kernel<<<dim3(MAXT, OUT / TN), 256, GSMEM>>>(bias, out);
}

// round 5
// speedup vs baseline: 2.1436x; 2.1436x over previous
#include <cuda_runtime.h>
#include <cuda_fp16.h>
#include <cstdint>

// Problem constants
#define NTOK 65536
#define IN   512
#define OUT  512
#define NE   8
#define NS   64

// GEMM tiling
#define TM 128
#define TN 256
#define KC 32
#define NCHUNK (IN / KC)          // 16
#define MAXT 576
#define LDSS 80                   // smem row stride (bytes): conflict-free ldmatrix

#define A_PLANE (TM * LDSS)       // 10240
#define B_PLANE (TN * LDSS)       // 20480
#define OFF_B   A_PLANE
#define STAGE_BYTES (A_PLANE + B_PLANE)       // 30720
#define STAGES 4
#define OFF_PERM (STAGES * STAGE_BYTES)       // 122880
#define GSMEM (OFF_PERM + 512)                // 123392

// ---------------- device scratch (static; no allocation) ---------------------
__device__ __half g_xh[(size_t)NTOK * IN];
__device__ __half g_Mh[(size_t)NS * OUT * IN];
__device__ int g_counts[NS];
__device__ int g_cursor[NS];
__device__ int g_perm[NTOK];
__device__ int g_tile_sys[MAXT];
__device__ int g_tile_start[MAXT];
__device__ int g_tile_rows[MAXT];

// ---------------- helpers -----------------------------------------------------
__device__ __forceinline__ uint32_t smem_u32(const void* p) {
    uint32_t a;
    asm("{ .reg .u64 t; cvta.to.shared.u64 t, %1; cvt.u32.u64 %0, t; }"
        : "=r"(a) : "l"(p));
    return a;
}
__device__ __forceinline__ void cpa16(uint32_t dst, const void* src) {
    asm volatile("cp.async.cg.shared.global [%0], [%1], 16;"
                 :: "r"(dst), "l"(src) : "memory");
}
__device__ __forceinline__ void ldsm4(uint32_t* r, uint32_t addr) {
    asm volatile("ldmatrix.sync.aligned.m8n8.x4.shared.b16 {%0,%1,%2,%3}, [%4];"
                 : "=r"(r[0]), "=r"(r[1]), "=r"(r[2]), "=r"(r[3]) : "r"(addr));
}
__device__ __forceinline__ void mma16816(float* c, const uint32_t* a,
                                         uint32_t b0, uint32_t b1) {
    asm volatile(
        "mma.sync.aligned.m16n8k16.row.col.f32.f16.f16.f32 "
        "{%0,%1,%2,%3}, {%4,%5,%6,%7}, {%8,%9}, {%0,%1,%2,%3};"
        : "+f"(c[0]), "+f"(c[1]), "+f"(c[2]), "+f"(c[3])
        : "r"(a[0]), "r"(a[1]), "r"(a[2]), "r"(a[3]), "r"(b0), "r"(b1));
}
__device__ __forceinline__ uint2 round4h(float4 v) {
    __half2 h01 = __floats2half2_rn(v.x, v.y);
    __half2 h23 = __floats2half2_rn(v.z, v.w);
    return make_uint2(*(uint32_t*)&h01, *(uint32_t*)&h23);
}

// ---------------- kernel 0: reset ---------------------------------------------
__global__ void init_kernel() {
    if (threadIdx.x < NS) g_counts[threadIdx.x] = 0;
}

// ---------------- kernel 1: histogram (block-aggregated) ----------------------
__global__ void hist_kernel(const int* __restrict__ bi) {
    __shared__ int h[NS];
    int tid = threadIdx.x;
    if (tid < NS) h[tid] = 0;
    __syncthreads();
    int n = blockIdx.x * blockDim.x + tid;
    atomicAdd(&h[bi[n]], 1);
    __syncthreads();
    if (tid < NS && h[tid] != 0) atomicAdd(&g_counts[tid], h[tid]);
}

// ---------------- kernel 2: scan + tile table ---------------------------------
__global__ void plan_kernel() {
    __shared__ int cnt[NS], offs[NS], tbase[NS];
    int tid = threadIdx.x;
    if (tid < NS) cnt[tid] = g_counts[tid];
    __syncthreads();
    if (tid == 0) {
        int off = 0, tb = 0;
        for (int s = 0; s < NS; ++s) {
            offs[s] = off; tbase[s] = tb;
            off += cnt[s];
            tb  += (cnt[s] + TM - 1) / TM;
        }
    }
    __syncthreads();
    for (int i = tid; i < MAXT; i += blockDim.x) g_tile_rows[i] = 0;
    __syncthreads();
    if (tid < NS) {
        int s = tid, c = cnt[s], nt = (c + TM - 1) / TM;
        int tb = tbase[s], off = offs[s];
        g_cursor[s] = off;
        for (int k = 0; k < nt; ++k) {
            g_tile_sys[tb + k]   = s;
            g_tile_start[tb + k] = off + k * TM;
            int rem = c - k * TM;
            g_tile_rows[tb + k]  = rem < TM ? rem : TM;
        }
    }
}

// ---------------- kernel 3: scatter (block-aggregated) ------------------------
__global__ void scatter_kernel(const int* __restrict__ bi) {
    __shared__ int lc[NS], lbase[NS];
    int tid = threadIdx.x;
    if (tid < NS) lc[tid] = 0;
    __syncthreads();
    int n = blockIdx.x * blockDim.x + tid;
    int s = bi[n];
    int r = atomicAdd(&lc[s], 1);
    __syncthreads();
    if (tid < NS && lc[tid] > 0) lbase[tid] = atomicAdd(&g_cursor[tid], lc[tid]);
    __syncthreads();
    g_perm[lbase[s] + r] = n;
}

// ---------------- kernel 4: gather + round x to fp16 (permuted) ---------------
__global__ __launch_bounds__(256) void prep_x(const float* __restrict__ x) {
    int idx = blockIdx.x * blockDim.x + threadIdx.x;   // over NTOK * 128
    int row = idx >> 7;
    int q   = idx & 127;
    int tok = g_perm[row];
    float4 v = ((const float4*)(x + (size_t)tok * IN))[q];
    ((uint2*)(g_xh + (size_t)row * IN))[q] = round4h(v);
}

// ---------------- kernel 5: mix weights -> fp16 plane -------------------------
__global__ __launch_bounds__(256) void mix_kernel(const float* __restrict__ W,
                                                  const float* __restrict__ coeff) {
    __shared__ float sc[NS * NE];
    int tid = threadIdx.x;
    for (int i = tid; i < NS * NE; i += blockDim.x) sc[i] = coeff[i];
    __syncthreads();

    int idx = blockIdx.x * blockDim.x + tid;   // over OUT*IN/4
    int o  = idx >> 7;
    int q  = idx & 127;
    int i4 = q * 4;

    float4 w[NE];
#pragma unroll
    for (int e = 0; e < NE; ++e)
        w[e] = *(const float4*)(W + (size_t)e * OUT * IN + o * IN + i4);

#pragma unroll 4
    for (int s = 0; s < NS; ++s) {
        float4 acc = make_float4(0.f, 0.f, 0.f, 0.f);
#pragma unroll
        for (int e = 0; e < NE; ++e) {
            float c = sc[s * NE + e];
            acc.x = fmaf(c, w[e].x, acc.x);
            acc.y = fmaf(c, w[e].y, acc.y);
            acc.z = fmaf(c, w[e].z, acc.z);
            acc.w = fmaf(c, w[e].w, acc.w);
        }
        ((uint2*)(g_Mh + (size_t)(s * OUT + o) * IN))[q] = round4h(acc);
    }
}

// ---------------- kernel 6: grouped GEMM, fp16 single-pass, 16 warps ----------
// CTA: 128 tokens x 256 outputs; 16 warps (2x8), warp tile 64x32.
// K=512 in 16 chunks of 32; 4-stage cp.async pipeline.
__global__ __launch_bounds__(512, 1) void gemm_kernel(const float* __restrict__ bias,
                                                      float* __restrict__ out) {
    int bt = blockIdx.x;
    int rows = g_tile_rows[bt];
    if (rows == 0) return;
    int sys       = g_tile_sys[bt];
    int row_start = g_tile_start[bt];
    int col0      = blockIdx.y * TN;

    extern __shared__ __align__(16) char smem[];
    uint32_t sm = smem_u32(smem);
    int tid = threadIdx.x, lane = tid & 31, wid = tid >> 5;
    int wm = wid >> 3, wn = wid & 7;      // 2 x 8 warp grid

    int* sperm = (int*)(smem + OFF_PERM);
    if (tid < TM) {
        int rsi = row_start + tid;
        if (rsi > NTOK - 1) rsi = NTOK - 1;
        sperm[tid] = g_perm[rsi];
    }

    // loaders: A = 128 rows x 4 segs (512 threads exactly); B = 256 rows x 4 segs (x2)
    int arow = tid >> 2;
    int ac   = tid & 3;
    size_t sysbase = (size_t)sys * OUT * IN;

    auto load_chunk = [&](int stage, int k0) {
        uint32_t sb = sm + stage * STAGE_BYTES;
        {
            int srcrow = row_start + arow;
            if (srcrow > NTOK - 1) srcrow = NTOK - 1;
            size_t goff = (size_t)srcrow * IN + k0 + ac * 8;
            cpa16(sb + arow * LDSS + ac * 16, g_xh + goff);
        }
#pragma unroll
        for (int h = 0; h < 2; ++h) {
            int row = arow + h * 128;
            size_t goff = sysbase + (size_t)(col0 + row) * IN + k0 + ac * 8;
            cpa16(sb + OFF_B + row * LDSS + ac * 16, g_Mh + goff);
        }
        asm volatile("cp.async.commit_group;" ::: "memory");
    };

    float acc[4][4][4];
#pragma unroll
    for (int mf = 0; mf < 4; ++mf)
#pragma unroll
        for (int nf = 0; nf < 4; ++nf)
#pragma unroll
            for (int r = 0; r < 4; ++r) acc[mf][nf][r] = 0.f;

    load_chunk(0, 0);
    load_chunk(1, KC);
    load_chunk(2, 2 * KC);

    int lrow = lane & 15, kseg = lane >> 4;
    uint32_t a_base = (uint32_t)((wm * 64 + lrow) * LDSS + kseg * 16);
    uint32_t b_base = (uint32_t)(OFF_B + (wn * 32 + lrow) * LDSS + kseg * 16);

#pragma unroll 1
    for (int c = 0; c < NCHUNK; ++c) {
        int rem = NCHUNK - 1 - c;
        if (rem >= 2)      asm volatile("cp.async.wait_group 2;" ::: "memory");
        else if (rem == 1) asm volatile("cp.async.wait_group 1;" ::: "memory");
        else               asm volatile("cp.async.wait_group 0;" ::: "memory");
        __syncthreads();
        uint32_t sb = sm + (c % STAGES) * STAGE_BYTES;

#pragma unroll
        for (int kk = 0; kk < 2; ++kk) {
            uint32_t aa[4][4], bb[2][4];
#pragma unroll
            for (int mf = 0; mf < 4; ++mf)
                ldsm4(aa[mf], sb + a_base + mf * 16 * LDSS + kk * 32);
#pragma unroll
            for (int bf = 0; bf < 2; ++bf)
                ldsm4(bb[bf], sb + b_base + bf * 16 * LDSS + kk * 32);
#pragma unroll
            for (int mf = 0; mf < 4; ++mf)
#pragma unroll
                for (int nf = 0; nf < 4; ++nf)
                    mma16816(acc[mf][nf], aa[mf],
                             bb[nf >> 1][nf & 1], bb[nf >> 1][(nf & 1) + 2]);
        }
        if (c + 3 < NCHUNK) load_chunk((c + 3) % STAGES, (c + 3) * KC);
    }

    // ---------------- epilogue: bias + scatter -------------------------------
    int g  = lane >> 2;
    int tc = (lane & 3) * 2;
    const float* bptr = bias + col0 + wn * 32 + tc;
    float2 bv[4];
#pragma unroll
    for (int nf = 0; nf < 4; ++nf)
        bv[nf] = make_float2(bptr[nf * 8], bptr[nf * 8 + 1]);

#pragma unroll
    for (int mf = 0; mf < 4; ++mf) {
#pragma unroll
        for (int rh = 0; rh < 2; ++rh) {
            int lr = wm * 64 + mf * 16 + rh * 8 + g;
            if (lr < rows) {
                float* orow = out + (size_t)sperm[lr] * OUT + col0 + wn * 32 + tc;
#pragma unroll
                for (int nf = 0; nf < 4; ++nf) {
                    float2 v = make_float2(acc[mf][nf][rh * 2]     + bv[nf].x,
                                           acc[mf][nf][rh * 2 + 1] + bv[nf].y);
                    *(float2*)(orow + nf * 8) = v;
                }
            }
        }
    }
}

// ---------------- launch -----------------------------------------------------
extern "C" void kernel_launch(void* const* d_in, const int* in_sizes, int n_in,
                              void* d_out, int out_size) {
    const float* x     = (const float*)d_in[0];
    const float* coeff = (const float*)d_in[1];
    const int*   bidx  = (const int*)d_in[2];
    const float* W     = (const float*)d_in[3];
    const float* bias  = (const float*)d_in[4];
    float*       out   = (float*)d_out;

    cudaFuncSetAttribute(gemm_kernel, cudaFuncAttributeMaxDynamicSharedMemorySize,
                         GSMEM);

    init_kernel<<<1, 64>>>();
    hist_kernel<<<NTOK / 1024, 1024>>>(bidx);
    plan_kernel<<<1, 256>>>();
    scatter_kernel<<<NTOK / 1024, 1024>>>(bidx);
    prep_x<<<NTOK * (IN / 4) / 256, 256>>>(x);
    mix_kernel<<<(OUT * IN / 4) / 256, 256>>>(W, coeff);
    gemm_kernel<<<dim3(MAXT, OUT / TN), 512, GSMEM>>>(bias, out);
}

// round 6
// speedup vs baseline: 2.2115x; 1.0317x over previous
#include <cuda_runtime.h>
#include <cuda_fp16.h>
#include <cstdint>

// Problem constants
#define NTOK 65536
#define IN   512
#define OUT  512
#define NE   8
#define NS   64

// GEMM tiling
#define TM 128
#define TN 256
#define KC 32
#define NCHUNK (IN / KC)          // 16
#define MAXT 576
#define LDSS 80                   // smem row stride (bytes): conflict-free ldmatrix

#define A_PLANE (TM * LDSS)       // 10240
#define B_PLANE (TN * LDSS)       // 20480
#define OFF_B   A_PLANE
#define STAGE_BYTES (A_PLANE + B_PLANE)       // 30720
#define STAGES 5
#define OFF_PERM (STAGES * STAGE_BYTES)       // 153600
#define GSMEM (OFF_PERM + 512)                // 154112

// ---------------- device scratch (static; no allocation) ---------------------
__device__ __half g_xh[(size_t)NTOK * IN];
__device__ __half g_Mh[(size_t)NS * OUT * IN];
__device__ int g_counts[NS];          // zero at load; gemm re-zeros for next replay
__device__ int g_cursor[NS];
__device__ int g_perm[NTOK];
__device__ int g_tile_sys[MAXT];
__device__ int g_tile_start[MAXT];
__device__ int g_tile_rows[MAXT];

// ---------------- helpers -----------------------------------------------------
__device__ __forceinline__ uint32_t smem_u32(const void* p) {
    uint32_t a;
    asm("{ .reg .u64 t; cvta.to.shared.u64 t, %1; cvt.u32.u64 %0, t; }"
        : "=r"(a) : "l"(p));
    return a;
}
__device__ __forceinline__ void cpa16(uint32_t dst, const void* src) {
    asm volatile("cp.async.cg.shared.global [%0], [%1], 16;"
                 :: "r"(dst), "l"(src) : "memory");
}
__device__ __forceinline__ void ldsm4(uint32_t* r, uint32_t addr) {
    asm volatile("ldmatrix.sync.aligned.m8n8.x4.shared.b16 {%0,%1,%2,%3}, [%4];"
                 : "=r"(r[0]), "=r"(r[1]), "=r"(r[2]), "=r"(r[3]) : "r"(addr));
}
__device__ __forceinline__ void mma16816(float* c, const uint32_t* a,
                                         uint32_t b0, uint32_t b1) {
    asm volatile(
        "mma.sync.aligned.m16n8k16.row.col.f32.f16.f16.f32 "
        "{%0,%1,%2,%3}, {%4,%5,%6,%7}, {%8,%9}, {%0,%1,%2,%3};"
        : "+f"(c[0]), "+f"(c[1]), "+f"(c[2]), "+f"(c[3])
        : "r"(a[0]), "r"(a[1]), "r"(a[2]), "r"(a[3]), "r"(b0), "r"(b1));
}
__device__ __forceinline__ uint2 round4h(float4 v) {
    __half2 h01 = __floats2half2_rn(v.x, v.y);
    __half2 h23 = __floats2half2_rn(v.z, v.w);
    return make_uint2(*(uint32_t*)&h01, *(uint32_t*)&h23);
}

// ---------------- kernel 1: fused mix (blocks 0..255) + hist (blocks 256..511)
__global__ __launch_bounds__(256) void mixhist_kernel(const float* __restrict__ W,
                                                      const float* __restrict__ coeff,
                                                      const int* __restrict__ bi) {
    int bx = blockIdx.x;
    int tid = threadIdx.x;
    if (bx < 256) {
        // ---- mix: M[s] = sum_e c[s,e] * W[e], rounded to fp16 ----
        __shared__ float sc[NS * NE];
        for (int i = tid; i < NS * NE; i += blockDim.x) sc[i] = coeff[i];
        __syncthreads();

        int idx = bx * 256 + tid;       // over OUT*IN/4
        int o  = idx >> 7;
        int q  = idx & 127;
        int i4 = q * 4;

        float4 w[NE];
#pragma unroll
        for (int e = 0; e < NE; ++e)
            w[e] = *(const float4*)(W + (size_t)e * OUT * IN + o * IN + i4);

#pragma unroll 4
        for (int s = 0; s < NS; ++s) {
            float4 acc = make_float4(0.f, 0.f, 0.f, 0.f);
#pragma unroll
            for (int e = 0; e < NE; ++e) {
                float c = sc[s * NE + e];
                acc.x = fmaf(c, w[e].x, acc.x);
                acc.y = fmaf(c, w[e].y, acc.y);
                acc.z = fmaf(c, w[e].z, acc.z);
                acc.w = fmaf(c, w[e].w, acc.w);
            }
            ((uint2*)(g_Mh + (size_t)(s * OUT + o) * IN))[q] = round4h(acc);
        }
    } else {
        // ---- histogram (block-aggregated) ----
        __shared__ int h[NS];
        if (tid < NS) h[tid] = 0;
        __syncthreads();
        int n = (bx - 256) * 256 + tid;
        atomicAdd(&h[bi[n]], 1);
        __syncthreads();
        if (tid < NS && h[tid] != 0) atomicAdd(&g_counts[tid], h[tid]);
    }
}

// ---------------- kernel 2: scan + tile table ---------------------------------
__global__ void plan_kernel() {
    __shared__ int cnt[NS], offs[NS], tbase[NS];
    int tid = threadIdx.x;
    if (tid < NS) cnt[tid] = g_counts[tid];
    __syncthreads();
    if (tid == 0) {
        int off = 0, tb = 0;
        for (int s = 0; s < NS; ++s) {
            offs[s] = off; tbase[s] = tb;
            off += cnt[s];
            tb  += (cnt[s] + TM - 1) / TM;
        }
    }
    __syncthreads();
    for (int i = tid; i < MAXT; i += blockDim.x) g_tile_rows[i] = 0;
    __syncthreads();
    if (tid < NS) {
        int s = tid, c = cnt[s], nt = (c + TM - 1) / TM;
        int tb = tbase[s], off = offs[s];
        g_cursor[s] = off;
        for (int k = 0; k < nt; ++k) {
            g_tile_sys[tb + k]   = s;
            g_tile_start[tb + k] = off + k * TM;
            int rem = c - k * TM;
            g_tile_rows[tb + k]  = rem < TM ? rem : TM;
        }
    }
}

// ---------------- kernel 3: scatter + gather/convert x rows -------------------
// Phase 1: compute permuted position per token (block-aggregated atomics).
// Phase 2: warp-cooperative copy of token rows fp32 -> fp16 into g_xh[pos].
__global__ __launch_bounds__(1024) void scatter_conv(const int* __restrict__ bi,
                                                     const float* __restrict__ x) {
    __shared__ int lc[NS], lbase[NS];
    __shared__ int spos[1024];
    int tid = threadIdx.x;
    if (tid < NS) lc[tid] = 0;
    __syncthreads();
    int n = blockIdx.x * 1024 + tid;
    int s = bi[n];
    int r = atomicAdd(&lc[s], 1);
    __syncthreads();
    if (tid < NS && lc[tid] > 0) lbase[tid] = atomicAdd(&g_cursor[tid], lc[tid]);
    __syncthreads();
    int pos = lbase[s] + r;
    g_perm[pos] = n;
    spos[tid] = pos;
    __syncthreads();

    // phase 2: warp w copies tokens [w*32, w*32+32)
    int lane = tid & 31, w = tid >> 5;
    int tokbase = blockIdx.x * 1024 + w * 32;
#pragma unroll 1
    for (int t = 0; t < 32; ++t) {
        int tok = tokbase + t;
        int p   = spos[w * 32 + t];
        const float4* src = (const float4*)(x + (size_t)tok * IN);
        uint2* dst = (uint2*)(g_xh + (size_t)p * IN);
#pragma unroll
        for (int pass = 0; pass < 4; ++pass) {
            int q = pass * 32 + lane;
            dst[q] = round4h(src[q]);
        }
    }
}

// ---------------- kernel 4: grouped GEMM, fp16 single-pass, 16 warps ----------
// CTA: 128 tokens x 256 outputs; 16 warps (2x8), warp tile 64x32.
// K=512 in 16 chunks of 32; 5-stage cp.async pipeline.
__global__ __launch_bounds__(512, 1) void gemm_kernel(const float* __restrict__ bias,
                                                      float* __restrict__ out) {
    // reset counts for the NEXT replay (stream-ordered: all readers already ran)
    if (blockIdx.x == 0 && blockIdx.y == 0 && threadIdx.x < NS)
        g_counts[threadIdx.x] = 0;

    int bt = blockIdx.x;
    int rows = g_tile_rows[bt];
    if (rows == 0) return;
    int sys       = g_tile_sys[bt];
    int row_start = g_tile_start[bt];
    int col0      = blockIdx.y * TN;

    extern __shared__ __align__(16) char smem[];
    uint32_t sm = smem_u32(smem);
    int tid = threadIdx.x, lane = tid & 31, wid = tid >> 5;
    int wm = wid >> 3, wn = wid & 7;      // 2 x 8 warp grid

    int* sperm = (int*)(smem + OFF_PERM);
    if (tid < TM) {
        int rsi = row_start + tid;
        if (rsi > NTOK - 1) rsi = NTOK - 1;
        sperm[tid] = g_perm[rsi];
    }

    int arow = tid >> 2;
    int ac   = tid & 3;
    size_t sysbase = (size_t)sys * OUT * IN;

    auto load_chunk = [&](int stage, int k0) {
        uint32_t sb = sm + stage * STAGE_BYTES;
        {
            int srcrow = row_start + arow;
            if (srcrow > NTOK - 1) srcrow = NTOK - 1;
            size_t goff = (size_t)srcrow * IN + k0 + ac * 8;
            cpa16(sb + arow * LDSS + ac * 16, g_xh + goff);
        }
#pragma unroll
        for (int h = 0; h < 2; ++h) {
            int row = arow + h * 128;
            size_t goff = sysbase + (size_t)(col0 + row) * IN + k0 + ac * 8;
            cpa16(sb + OFF_B + row * LDSS + ac * 16, g_Mh + goff);
        }
        asm volatile("cp.async.commit_group;" ::: "memory");
    };

    float acc[4][4][4];
#pragma unroll
    for (int mf = 0; mf < 4; ++mf)
#pragma unroll
        for (int nf = 0; nf < 4; ++nf)
#pragma unroll
            for (int r = 0; r < 4; ++r) acc[mf][nf][r] = 0.f;

    load_chunk(0, 0);
    load_chunk(1, KC);
    load_chunk(2, 2 * KC);
    load_chunk(3, 3 * KC);

    int lrow = lane & 15, kseg = lane >> 4;
    uint32_t a_base = (uint32_t)((wm * 64 + lrow) * LDSS + kseg * 16);
    uint32_t b_base = (uint32_t)(OFF_B + (wn * 32 + lrow) * LDSS + kseg * 16);

#pragma unroll 1
    for (int c = 0; c < NCHUNK; ++c) {
        int rem = NCHUNK - 1 - c;
        if (rem >= 3)      asm volatile("cp.async.wait_group 3;" ::: "memory");
        else if (rem == 2) asm volatile("cp.async.wait_group 2;" ::: "memory");
        else if (rem == 1) asm volatile("cp.async.wait_group 1;" ::: "memory");
        else               asm volatile("cp.async.wait_group 0;" ::: "memory");
        __syncthreads();
        uint32_t sb = sm + (c % STAGES) * STAGE_BYTES;

#pragma unroll
        for (int kk = 0; kk < 2; ++kk) {
            uint32_t aa[4][4], bb[2][4];
#pragma unroll
            for (int mf = 0; mf < 4; ++mf)
                ldsm4(aa[mf], sb + a_base + mf * 16 * LDSS + kk * 32);
#pragma unroll
            for (int bf = 0; bf < 2; ++bf)
                ldsm4(bb[bf], sb + b_base + bf * 16 * LDSS + kk * 32);
#pragma unroll
            for (int mf = 0; mf < 4; ++mf)
#pragma unroll
                for (int nf = 0; nf < 4; ++nf)
                    mma16816(acc[mf][nf], aa[mf],
                             bb[nf >> 1][nf & 1], bb[nf >> 1][(nf & 1) + 2]);
        }
        if (c + 4 < NCHUNK) load_chunk((c + 4) % STAGES, (c + 4) * KC);
    }

    // ---------------- epilogue: bias + scatter -------------------------------
    int g  = lane >> 2;
    int tc = (lane & 3) * 2;
    const float* bptr = bias + col0 + wn * 32 + tc;
    float2 bv[4];
#pragma unroll
    for (int nf = 0; nf < 4; ++nf)
        bv[nf] = make_float2(bptr[nf * 8], bptr[nf * 8 + 1]);

#pragma unroll
    for (int mf = 0; mf < 4; ++mf) {
#pragma unroll
        for (int rh = 0; rh < 2; ++rh) {
            int lr = wm * 64 + mf * 16 + rh * 8 + g;
            if (lr < rows) {
                float* orow = out + (size_t)sperm[lr] * OUT + col0 + wn * 32 + tc;
#pragma unroll
                for (int nf = 0; nf < 4; ++nf) {
                    float2 v = make_float2(acc[mf][nf][rh * 2]     + bv[nf].x,
                                           acc[mf][nf][rh * 2 + 1] + bv[nf].y);
                    *(float2*)(orow + nf * 8) = v;
                }
            }
        }
    }
}

// ---------------- launch -----------------------------------------------------
extern "C" void kernel_launch(void* const* d_in, const int* in_sizes, int n_in,
                              void* d_out, int out_size) {
    const float* x     = (const float*)d_in[0];
    const float* coeff = (const float*)d_in[1];
    const int*   bidx  = (const int*)d_in[2];
    const float* W     = (const float*)d_in[3];
    const float* bias  = (const float*)d_in[4];
    float*       out   = (float*)d_out;

    cudaFuncSetAttribute(gemm_kernel, cudaFuncAttributeMaxDynamicSharedMemorySize,
                         GSMEM);

    mixhist_kernel<<<512, 256>>>(W, coeff, bidx);
    plan_kernel<<<1, 256>>>();
    scatter_conv<<<NTOK / 1024, 1024>>>(bidx, x);
    gemm_kernel<<<dim3(MAXT, OUT / TN), 512, GSMEM>>>(bias, out);
}

// round 7
// speedup vs baseline: 2.2795x; 1.0307x over previous
#include <cuda_runtime.h>
#include <cuda_fp16.h>
#include <cstdint>

// Problem constants
#define NTOK 65536
#define IN   512
#define OUT  512
#define NE   8
#define NS   64

// GEMM tiling
#define TM 128
#define TN 256
#define KC 64
#define NCHUNK (IN / KC)          // 8
#define MAXT 576
#define LDSS 144                  // 128B data + 16B pad: conflict-free ldmatrix

#define A_PLANE (TM * LDSS)       // 18432
#define B_PLANE (TN * LDSS)       // 36864
#define OFF_B   A_PLANE
#define STAGE_BYTES (A_PLANE + B_PLANE)       // 55296
#define STAGES 3
#define OFF_PERM (STAGES * STAGE_BYTES)       // 165888
#define GSMEM (OFF_PERM + 512)                // 166400

// ---------------- device scratch (static; no allocation) ---------------------
__device__ __half g_xh[(size_t)NTOK * IN];
__device__ __half g_Mh[(size_t)NS * OUT * IN];
__device__ int g_counts[NS];          // zero at load; gemm re-zeros for next replay
__device__ int g_cursor[NS];
__device__ int g_perm[NTOK];
__device__ int g_tile_sys[MAXT];
__device__ int g_tile_start[MAXT];
__device__ int g_tile_rows[MAXT];

// ---------------- helpers -----------------------------------------------------
__device__ __forceinline__ uint32_t smem_u32(const void* p) {
    uint32_t a;
    asm("{ .reg .u64 t; cvta.to.shared.u64 t, %1; cvt.u32.u64 %0, t; }"
        : "=r"(a) : "l"(p));
    return a;
}
__device__ __forceinline__ void cpa16(uint32_t dst, const void* src) {
    asm volatile("cp.async.cg.shared.global [%0], [%1], 16;"
                 :: "r"(dst), "l"(src) : "memory");
}
__device__ __forceinline__ void ldsm4(uint32_t* r, uint32_t addr) {
    asm volatile("ldmatrix.sync.aligned.m8n8.x4.shared.b16 {%0,%1,%2,%3}, [%4];"
                 : "=r"(r[0]), "=r"(r[1]), "=r"(r[2]), "=r"(r[3]) : "r"(addr));
}
__device__ __forceinline__ void mma16816(float* c, const uint32_t* a,
                                         uint32_t b0, uint32_t b1) {
    asm volatile(
        "mma.sync.aligned.m16n8k16.row.col.f32.f16.f16.f32 "
        "{%0,%1,%2,%3}, {%4,%5,%6,%7}, {%8,%9}, {%0,%1,%2,%3};"
        : "+f"(c[0]), "+f"(c[1]), "+f"(c[2]), "+f"(c[3])
        : "r"(a[0]), "r"(a[1]), "r"(a[2]), "r"(a[3]), "r"(b0), "r"(b1));
}
__device__ __forceinline__ uint2 round4h(float4 v) {
    __half2 h01 = __floats2half2_rn(v.x, v.y);
    __half2 h23 = __floats2half2_rn(v.z, v.w);
    return make_uint2(*(uint32_t*)&h01, *(uint32_t*)&h23);
}

// ---------------- kernel 1: fused mix (blocks 0..255) + hist (blocks 256..511)
__global__ __launch_bounds__(256) void mixhist_kernel(const float* __restrict__ W,
                                                      const float* __restrict__ coeff,
                                                      const int* __restrict__ bi) {
    int bx = blockIdx.x;
    int tid = threadIdx.x;
    if (bx < 256) {
        __shared__ float sc[NS * NE];
        for (int i = tid; i < NS * NE; i += blockDim.x) sc[i] = coeff[i];
        __syncthreads();

        int idx = bx * 256 + tid;       // over OUT*IN/4
        int o  = idx >> 7;
        int q  = idx & 127;
        int i4 = q * 4;

        float4 w[NE];
#pragma unroll
        for (int e = 0; e < NE; ++e)
            w[e] = *(const float4*)(W + (size_t)e * OUT * IN + o * IN + i4);

#pragma unroll 4
        for (int s = 0; s < NS; ++s) {
            float4 acc = make_float4(0.f, 0.f, 0.f, 0.f);
#pragma unroll
            for (int e = 0; e < NE; ++e) {
                float c = sc[s * NE + e];
                acc.x = fmaf(c, w[e].x, acc.x);
                acc.y = fmaf(c, w[e].y, acc.y);
                acc.z = fmaf(c, w[e].z, acc.z);
                acc.w = fmaf(c, w[e].w, acc.w);
            }
            ((uint2*)(g_Mh + (size_t)(s * OUT + o) * IN))[q] = round4h(acc);
        }
    } else {
        __shared__ int h[NS];
        if (tid < NS) h[tid] = 0;
        __syncthreads();
        int n = (bx - 256) * 256 + tid;
        atomicAdd(&h[bi[n]], 1);
        __syncthreads();
        if (tid < NS && h[tid] != 0) atomicAdd(&g_counts[tid], h[tid]);
    }
}

// ---------------- kernel 2: scan + tile table ---------------------------------
__global__ void plan_kernel() {
    __shared__ int cnt[NS], offs[NS], tbase[NS];
    int tid = threadIdx.x;
    if (tid < NS) cnt[tid] = g_counts[tid];
    __syncthreads();
    if (tid == 0) {
        int off = 0, tb = 0;
        for (int s = 0; s < NS; ++s) {
            offs[s] = off; tbase[s] = tb;
            off += cnt[s];
            tb  += (cnt[s] + TM - 1) / TM;
        }
    }
    __syncthreads();
    for (int i = tid; i < MAXT; i += blockDim.x) g_tile_rows[i] = 0;
    __syncthreads();
    if (tid < NS) {
        int s = tid, c = cnt[s], nt = (c + TM - 1) / TM;
        int tb = tbase[s], off = offs[s];
        g_cursor[s] = off;
        for (int k = 0; k < nt; ++k) {
            g_tile_sys[tb + k]   = s;
            g_tile_start[tb + k] = off + k * TM;
            int rem = c - k * TM;
            g_tile_rows[tb + k]  = rem < TM ? rem : TM;
        }
    }
}

// ---------------- kernel 3: scatter + gather/convert x rows -------------------
__global__ __launch_bounds__(1024) void scatter_conv(const int* __restrict__ bi,
                                                     const float* __restrict__ x) {
    __shared__ int lc[NS], lbase[NS];
    __shared__ int spos[1024];
    int tid = threadIdx.x;
    if (tid < NS) lc[tid] = 0;
    __syncthreads();
    int n = blockIdx.x * 1024 + tid;
    int s = bi[n];
    int r = atomicAdd(&lc[s], 1);
    __syncthreads();
    if (tid < NS && lc[tid] > 0) lbase[tid] = atomicAdd(&g_cursor[tid], lc[tid]);
    __syncthreads();
    int pos = lbase[s] + r;
    g_perm[pos] = n;
    spos[tid] = pos;
    __syncthreads();

    int lane = tid & 31, w = tid >> 5;
    int tokbase = blockIdx.x * 1024 + w * 32;
#pragma unroll 1
    for (int t = 0; t < 32; ++t) {
        int tok = tokbase + t;
        int p   = spos[w * 32 + t];
        const float4* src = (const float4*)(x + (size_t)tok * IN);
        uint2* dst = (uint2*)(g_xh + (size_t)p * IN);
#pragma unroll
        for (int pass = 0; pass < 4; ++pass) {
            int q = pass * 32 + lane;
            dst[q] = round4h(src[q]);
        }
    }
}

// ---------------- kernel 4: grouped GEMM, fp16, 16 warps, kk-pipelined --------
// CTA: 128 tokens x 256 outputs; 16 warps (2x8), warp tile 64x32.
// K=512 in 8 chunks of 64; 3-stage cp.async pipeline; double-buffered fragments.
__global__ __launch_bounds__(512, 1) void gemm_kernel(const float* __restrict__ bias,
                                                      float* __restrict__ out) {
    if (blockIdx.x == 0 && blockIdx.y == 0 && threadIdx.x < NS)
        g_counts[threadIdx.x] = 0;

    int bt = blockIdx.x;
    int rows = g_tile_rows[bt];
    if (rows == 0) return;
    int sys       = g_tile_sys[bt];
    int row_start = g_tile_start[bt];
    int col0      = blockIdx.y * TN;

    extern __shared__ __align__(16) char smem[];
    uint32_t sm = smem_u32(smem);
    int tid = threadIdx.x, lane = tid & 31, wid = tid >> 5;
    int wm = wid >> 3, wn = wid & 7;      // 2 x 8 warp grid

    int* sperm = (int*)(smem + OFF_PERM);
    if (tid < TM) {
        int rsi = row_start + tid;
        if (rsi > NTOK - 1) rsi = NTOK - 1;
        sperm[tid] = g_perm[rsi];
    }

    // loaders: 512 threads; A: 128 rows x 8 segs (2 rows/thread);
    //          B: 256 rows x 8 segs (4 rows/thread). 16B per cp.async.
    int lrow8 = tid >> 3;     // 0..63
    int seg   = tid & 7;
    size_t sysbase = (size_t)sys * OUT * IN;

    auto load_chunk = [&](int stage, int k0) {
        uint32_t sb = sm + stage * STAGE_BYTES;
#pragma unroll
        for (int h = 0; h < 2; ++h) {
            int row = lrow8 + h * 64;
            int srcrow = row_start + row;
            if (srcrow > NTOK - 1) srcrow = NTOK - 1;
            cpa16(sb + row * LDSS + seg * 16,
                  g_xh + (size_t)srcrow * IN + k0 + seg * 8);
        }
#pragma unroll
        for (int h = 0; h < 4; ++h) {
            int row = lrow8 + h * 64;
            cpa16(sb + OFF_B + row * LDSS + seg * 16,
                  g_Mh + sysbase + (size_t)(col0 + row) * IN + k0 + seg * 8);
        }
        asm volatile("cp.async.commit_group;" ::: "memory");
    };

    float acc[4][4][4];
#pragma unroll
    for (int mf = 0; mf < 4; ++mf)
#pragma unroll
        for (int nf = 0; nf < 4; ++nf)
#pragma unroll
            for (int r = 0; r < 4; ++r) acc[mf][nf][r] = 0.f;

    load_chunk(0, 0);
    load_chunk(1, KC);

    int lrow = lane & 15, kseg = lane >> 4;
    uint32_t a_base = (uint32_t)((wm * 64 + lrow) * LDSS + kseg * 16);
    uint32_t b_base = (uint32_t)(OFF_B + (wn * 32 + lrow) * LDSS + kseg * 16);

    uint32_t aa[2][4][4], bb[2][2][4];

#pragma unroll 1
    for (int c = 0; c < NCHUNK; ++c) {
        if (c < NCHUNK - 1) asm volatile("cp.async.wait_group 1;" ::: "memory");
        else                asm volatile("cp.async.wait_group 0;" ::: "memory");
        __syncthreads();
        if (c + 2 < NCHUNK) load_chunk((c + 2) % STAGES, (c + 2) * KC);

        uint32_t sb = sm + (c % STAGES) * STAGE_BYTES;

        // prologue: fragments for kk=0
#pragma unroll
        for (int mf = 0; mf < 4; ++mf)
            ldsm4(aa[0][mf], sb + a_base + mf * 16 * LDSS);
#pragma unroll
        for (int bf = 0; bf < 2; ++bf)
            ldsm4(bb[0][bf], sb + b_base + bf * 16 * LDSS);

#pragma unroll
        for (int kk = 0; kk < 4; ++kk) {
            int cur = kk & 1;
            if (kk < 3) {
                int nxt = cur ^ 1;
#pragma unroll
                for (int mf = 0; mf < 4; ++mf)
                    ldsm4(aa[nxt][mf], sb + a_base + mf * 16 * LDSS + (kk + 1) * 32);
#pragma unroll
                for (int bf = 0; bf < 2; ++bf)
                    ldsm4(bb[nxt][bf], sb + b_base + bf * 16 * LDSS + (kk + 1) * 32);
            }
#pragma unroll
            for (int mf = 0; mf < 4; ++mf)
#pragma unroll
                for (int nf = 0; nf < 4; ++nf)
                    mma16816(acc[mf][nf], aa[cur][mf],
                             bb[cur][nf >> 1][nf & 1], bb[cur][nf >> 1][(nf & 1) + 2]);
        }
    }

    // ---------------- epilogue: bias + scatter -------------------------------
    int g  = lane >> 2;
    int tc = (lane & 3) * 2;
    const float* bptr = bias + col0 + wn * 32 + tc;
    float2 bv[4];
#pragma unroll
    for (int nf = 0; nf < 4; ++nf)
        bv[nf] = make_float2(bptr[nf * 8], bptr[nf * 8 + 1]);

#pragma unroll
    for (int mf = 0; mf < 4; ++mf) {
#pragma unroll
        for (int rh = 0; rh < 2; ++rh) {
            int lr = wm * 64 + mf * 16 + rh * 8 + g;
            if (lr < rows) {
                float* orow = out + (size_t)sperm[lr] * OUT + col0 + wn * 32 + tc;
#pragma unroll
                for (int nf = 0; nf < 4; ++nf) {
                    float2 v = make_float2(acc[mf][nf][rh * 2]     + bv[nf].x,
                                           acc[mf][nf][rh * 2 + 1] + bv[nf].y);
                    *(float2*)(orow + nf * 8) = v;
                }
            }
        }
    }
}

// ---------------- launch -----------------------------------------------------
extern "C" void kernel_launch(void* const* d_in, const int* in_sizes, int n_in,
                              void* d_out, int out_size) {
    const float* x     = (const float*)d_in[0];
    const float* coeff = (const float*)d_in[1];
    const int*   bidx  = (const int*)d_in[2];
    const float* W     = (const float*)d_in[3];
    const float* bias  = (const float*)d_in[4];
    float*       out   = (float*)d_out;

    cudaFuncSetAttribute(gemm_kernel, cudaFuncAttributeMaxDynamicSharedMemorySize,
                         GSMEM);

    mixhist_kernel<<<512, 256>>>(W, coeff, bidx);
    plan_kernel<<<1, 256>>>();
    scatter_conv<<<NTOK / 1024, 1024>>>(bidx, x);
    gemm_kernel<<<dim3(MAXT, OUT / TN), 512, GSMEM>>>(bias, out);
}

// round 8
// speedup vs baseline: 2.5384x; 1.1136x over previous
#include <cuda_runtime.h>
#include <cuda_fp16.h>
#include <cstdint>

// Problem constants
#define NTOK 65536
#define IN   512
#define OUT  512
#define NE   8
#define NS   64

// GEMM tiling
#define TM 128
#define TN 128
#define KC 64
#define NCHUNK (IN / KC)          // 8
#define MAXT 576
#define LDSS 144                  // 128B data + 16B pad: conflict-free ldmatrix

#define A_PLANE (TM * LDSS)       // 18432
#define B_PLANE (TN * LDSS)       // 18432
#define OFF_B   A_PLANE
#define STAGE_BYTES (A_PLANE + B_PLANE)       // 36864
#define STAGES 3
#define OFF_PERM (STAGES * STAGE_BYTES)       // 110592
#define GSMEM (OFF_PERM + 512)                // 111104  (2 CTAs/SM fit in 228KB)

// ---------------- device scratch (static; no allocation) ---------------------
__device__ __half g_xh[(size_t)NTOK * IN];
__device__ __half g_Mh[(size_t)NS * OUT * IN];
__device__ int g_counts[NS];          // zero at load; gemm re-zeros for next replay
__device__ int g_cursor[NS];
__device__ int g_perm[NTOK];
__device__ int g_tile_sys[MAXT];
__device__ int g_tile_start[MAXT];
__device__ int g_tile_rows[MAXT];

// ---------------- helpers -----------------------------------------------------
__device__ __forceinline__ uint32_t smem_u32(const void* p) {
    uint32_t a;
    asm("{ .reg .u64 t; cvta.to.shared.u64 t, %1; cvt.u32.u64 %0, t; }"
        : "=r"(a) : "l"(p));
    return a;
}
__device__ __forceinline__ void cpa16(uint32_t dst, const void* src) {
    asm volatile("cp.async.cg.shared.global [%0], [%1], 16;"
                 :: "r"(dst), "l"(src) : "memory");
}
__device__ __forceinline__ void ldsm4(uint32_t* r, uint32_t addr) {
    asm volatile("ldmatrix.sync.aligned.m8n8.x4.shared.b16 {%0,%1,%2,%3}, [%4];"
                 : "=r"(r[0]), "=r"(r[1]), "=r"(r[2]), "=r"(r[3]) : "r"(addr));
}
__device__ __forceinline__ void mma16816(float* c, const uint32_t* a,
                                         uint32_t b0, uint32_t b1) {
    asm volatile(
        "mma.sync.aligned.m16n8k16.row.col.f32.f16.f16.f32 "
        "{%0,%1,%2,%3}, {%4,%5,%6,%7}, {%8,%9}, {%0,%1,%2,%3};"
        : "+f"(c[0]), "+f"(c[1]), "+f"(c[2]), "+f"(c[3])
        : "r"(a[0]), "r"(a[1]), "r"(a[2]), "r"(a[3]), "r"(b0), "r"(b1));
}
__device__ __forceinline__ uint2 round4h(float4 v) {
    __half2 h01 = __floats2half2_rn(v.x, v.y);
    __half2 h23 = __floats2half2_rn(v.z, v.w);
    return make_uint2(*(uint32_t*)&h01, *(uint32_t*)&h23);
}

// ---------------- kernel 1: fused mix (blocks 0..255) + hist (blocks 256..511)
__global__ __launch_bounds__(256) void mixhist_kernel(const float* __restrict__ W,
                                                      const float* __restrict__ coeff,
                                                      const int* __restrict__ bi) {
    int bx = blockIdx.x;
    int tid = threadIdx.x;
    if (bx < 256) {
        __shared__ float sc[NS * NE];
        for (int i = tid; i < NS * NE; i += blockDim.x) sc[i] = coeff[i];
        __syncthreads();

        int idx = bx * 256 + tid;       // over OUT*IN/4
        int o  = idx >> 7;
        int q  = idx & 127;
        int i4 = q * 4;

        float4 w[NE];
#pragma unroll
        for (int e = 0; e < NE; ++e)
            w[e] = *(const float4*)(W + (size_t)e * OUT * IN + o * IN + i4);

#pragma unroll 4
        for (int s = 0; s < NS; ++s) {
            float4 acc = make_float4(0.f, 0.f, 0.f, 0.f);
#pragma unroll
            for (int e = 0; e < NE; ++e) {
                float c = sc[s * NE + e];
                acc.x = fmaf(c, w[e].x, acc.x);
                acc.y = fmaf(c, w[e].y, acc.y);
                acc.z = fmaf(c, w[e].z, acc.z);
                acc.w = fmaf(c, w[e].w, acc.w);
            }
            ((uint2*)(g_Mh + (size_t)(s * OUT + o) * IN))[q] = round4h(acc);
        }
    } else {
        __shared__ int h[NS];
        if (tid < NS) h[tid] = 0;
        __syncthreads();
        int n = (bx - 256) * 256 + tid;
        atomicAdd(&h[bi[n]], 1);
        __syncthreads();
        if (tid < NS && h[tid] != 0) atomicAdd(&g_counts[tid], h[tid]);
    }
}

// ---------------- kernel 2: scan + tile table ---------------------------------
__global__ void plan_kernel() {
    __shared__ int cnt[NS], offs[NS], tbase[NS];
    int tid = threadIdx.x;
    if (tid < NS) cnt[tid] = g_counts[tid];
    __syncthreads();
    if (tid == 0) {
        int off = 0, tb = 0;
        for (int s = 0; s < NS; ++s) {
            offs[s] = off; tbase[s] = tb;
            off += cnt[s];
            tb  += (cnt[s] + TM - 1) / TM;
        }
    }
    __syncthreads();
    for (int i = tid; i < MAXT; i += blockDim.x) g_tile_rows[i] = 0;
    __syncthreads();
    if (tid < NS) {
        int s = tid, c = cnt[s], nt = (c + TM - 1) / TM;
        int tb = tbase[s], off = offs[s];
        g_cursor[s] = off;
        for (int k = 0; k < nt; ++k) {
            g_tile_sys[tb + k]   = s;
            g_tile_start[tb + k] = off + k * TM;
            int rem = c - k * TM;
            g_tile_rows[tb + k]  = rem < TM ? rem : TM;
        }
    }
}

// ---------------- kernel 3: scatter + gather/convert x rows -------------------
__global__ __launch_bounds__(1024) void scatter_conv(const int* __restrict__ bi,
                                                     const float* __restrict__ x) {
    __shared__ int lc[NS], lbase[NS];
    __shared__ int spos[1024];
    int tid = threadIdx.x;
    if (tid < NS) lc[tid] = 0;
    __syncthreads();
    int n = blockIdx.x * 1024 + tid;
    int s = bi[n];
    int r = atomicAdd(&lc[s], 1);
    __syncthreads();
    if (tid < NS && lc[tid] > 0) lbase[tid] = atomicAdd(&g_cursor[tid], lc[tid]);
    __syncthreads();
    int pos = lbase[s] + r;
    g_perm[pos] = n;
    spos[tid] = pos;
    __syncthreads();

    int lane = tid & 31, w = tid >> 5;
    int tokbase = blockIdx.x * 1024 + w * 32;
#pragma unroll 1
    for (int t = 0; t < 32; ++t) {
        int tok = tokbase + t;
        int p   = spos[w * 32 + t];
        const float4* src = (const float4*)(x + (size_t)tok * IN);
        uint2* dst = (uint2*)(g_xh + (size_t)p * IN);
#pragma unroll
        for (int pass = 0; pass < 4; ++pass) {
            int q = pass * 32 + lane;
            dst[q] = round4h(src[q]);
        }
    }
}

// ---------------- kernel 4: grouped GEMM, fp16, 8 warps, 2 CTAs/SM ------------
// CTA: 128 tokens x 128 outputs; 8 warps (2x4), warp tile 64x32.
// K=512 in 8 chunks of 64; 3-stage cp.async pipeline; double-buffered fragments.
__global__ __launch_bounds__(256, 2) void gemm_kernel(const float* __restrict__ bias,
                                                      float* __restrict__ out) {
    if (blockIdx.x == 0 && blockIdx.y == 0 && threadIdx.x < NS)
        g_counts[threadIdx.x] = 0;

    int bt = blockIdx.x;
    int rows = g_tile_rows[bt];
    if (rows == 0) return;
    int sys       = g_tile_sys[bt];
    int row_start = g_tile_start[bt];
    int col0      = blockIdx.y * TN;

    extern __shared__ __align__(16) char smem[];
    uint32_t sm = smem_u32(smem);
    int tid = threadIdx.x, lane = tid & 31, wid = tid >> 5;
    int wm = wid >> 2, wn = wid & 3;      // 2 x 4 warp grid

    int* sperm = (int*)(smem + OFF_PERM);
    if (tid < TM) {
        int rsi = row_start + tid;
        if (rsi > NTOK - 1) rsi = NTOK - 1;
        sperm[tid] = g_perm[rsi];
    }

    // loaders: 256 threads; A: 128 rows x 8 segs (4 rows/thread);
    //          B: 128 rows x 8 segs (4 rows/thread). 16B per cp.async.
    int row32 = tid >> 3;     // 0..31
    int seg   = tid & 7;
    size_t sysbase = (size_t)sys * OUT * IN;

    auto load_chunk = [&](int stage, int k0) {
        uint32_t sb = sm + stage * STAGE_BYTES;
#pragma unroll
        for (int h = 0; h < 4; ++h) {
            int row = row32 + h * 32;
            int srcrow = row_start + row;
            if (srcrow > NTOK - 1) srcrow = NTOK - 1;
            cpa16(sb + row * LDSS + seg * 16,
                  g_xh + (size_t)srcrow * IN + k0 + seg * 8);
        }
#pragma unroll
        for (int h = 0; h < 4; ++h) {
            int row = row32 + h * 32;
            cpa16(sb + OFF_B + row * LDSS + seg * 16,
                  g_Mh + sysbase + (size_t)(col0 + row) * IN + k0 + seg * 8);
        }
        asm volatile("cp.async.commit_group;" ::: "memory");
    };

    float acc[4][4][4];
#pragma unroll
    for (int mf = 0; mf < 4; ++mf)
#pragma unroll
        for (int nf = 0; nf < 4; ++nf)
#pragma unroll
            for (int r = 0; r < 4; ++r) acc[mf][nf][r] = 0.f;

    load_chunk(0, 0);
    load_chunk(1, KC);

    int lrow = lane & 15, kseg = lane >> 4;
    uint32_t a_base = (uint32_t)((wm * 64 + lrow) * LDSS + kseg * 16);
    uint32_t b_base = (uint32_t)(OFF_B + (wn * 32 + lrow) * LDSS + kseg * 16);

    uint32_t aa[2][4][4], bb[2][2][4];

#pragma unroll 1
    for (int c = 0; c < NCHUNK; ++c) {
        if (c < NCHUNK - 1) asm volatile("cp.async.wait_group 1;" ::: "memory");
        else                asm volatile("cp.async.wait_group 0;" ::: "memory");
        __syncthreads();
        if (c + 2 < NCHUNK) load_chunk((c + 2) % STAGES, (c + 2) * KC);

        uint32_t sb = sm + (c % STAGES) * STAGE_BYTES;

        // prologue: fragments for kk=0
#pragma unroll
        for (int mf = 0; mf < 4; ++mf)
            ldsm4(aa[0][mf], sb + a_base + mf * 16 * LDSS);
#pragma unroll
        for (int bf = 0; bf < 2; ++bf)
            ldsm4(bb[0][bf], sb + b_base + bf * 16 * LDSS);

#pragma unroll
        for (int kk = 0; kk < 4; ++kk) {
            int cur = kk & 1;
            if (kk < 3) {
                int nxt = cur ^ 1;
#pragma unroll
                for (int mf = 0; mf < 4; ++mf)
                    ldsm4(aa[nxt][mf], sb + a_base + mf * 16 * LDSS + (kk + 1) * 32);
#pragma unroll
                for (int bf = 0; bf < 2; ++bf)
                    ldsm4(bb[nxt][bf], sb + b_base + bf * 16 * LDSS + (kk + 1) * 32);
            }
#pragma unroll
            for (int mf = 0; mf < 4; ++mf)
#pragma unroll
                for (int nf = 0; nf < 4; ++nf)
                    mma16816(acc[mf][nf], aa[cur][mf],
                             bb[cur][nf >> 1][nf & 1], bb[cur][nf >> 1][(nf & 1) + 2]);
        }
    }

    // ---------------- epilogue: bias + scatter -------------------------------
    int g  = lane >> 2;
    int tc = (lane & 3) * 2;
    const float* bptr = bias + col0 + wn * 32 + tc;
    float2 bv[4];
#pragma unroll
    for (int nf = 0; nf < 4; ++nf)
        bv[nf] = make_float2(bptr[nf * 8], bptr[nf * 8 + 1]);

#pragma unroll
    for (int mf = 0; mf < 4; ++mf) {
#pragma unroll
        for (int rh = 0; rh < 2; ++rh) {
            int lr = wm * 64 + mf * 16 + rh * 8 + g;
            if (lr < rows) {
                float* orow = out + (size_t)sperm[lr] * OUT + col0 + wn * 32 + tc;
#pragma unroll
                for (int nf = 0; nf < 4; ++nf) {
                    float2 v = make_float2(acc[mf][nf][rh * 2]     + bv[nf].x,
                                           acc[mf][nf][rh * 2 + 1] + bv[nf].y);
                    *(float2*)(orow + nf * 8) = v;
                }
            }
        }
    }
}

// ---------------- launch -----------------------------------------------------
extern "C" void kernel_launch(void* const* d_in, const int* in_sizes, int n_in,
                              void* d_out, int out_size) {
    const float* x     = (const float*)d_in[0];
    const float* coeff = (const float*)d_in[1];
    const int*   bidx  = (const int*)d_in[2];
    const float* W     = (const float*)d_in[3];
    const float* bias  = (const float*)d_in[4];
    float*       out   = (float*)d_out;

    cudaFuncSetAttribute(gemm_kernel, cudaFuncAttributeMaxDynamicSharedMemorySize,
                         GSMEM);

    mixhist_kernel<<<512, 256>>>(W, coeff, bidx);
    plan_kernel<<<1, 256>>>();
    scatter_conv<<<NTOK / 1024, 1024>>>(bidx, x);
    gemm_kernel<<<dim3(MAXT, OUT / TN), 256, GSMEM>>>(bias, out);
}

// round 9
// speedup vs baseline: 2.5871x; 1.0192x over previous
#include <cuda_runtime.h>
#include <cuda_fp16.h>
#include <cstdint>

// Problem constants
#define NTOK 65536
#define IN   512
#define OUT  512
#define NE   8
#define NS   64

// GEMM tiling
#define TM 128
#define TN 64
#define KC 64
#define NCHUNK (IN / KC)          // 8
#define MAXT 576
#define LDSS 144                  // 128B data + 16B pad: conflict-free ldmatrix

#define A_PLANE (TM * LDSS)       // 18432
#define B_PLANE (TN * LDSS)       // 9216
#define OFF_B   A_PLANE
#define STAGE_BYTES (A_PLANE + B_PLANE)       // 27648
#define STAGES 2
#define OFF_PERM (STAGES * STAGE_BYTES)       // 55296
#define GSMEM (OFF_PERM + 512)                // 55808  (4 CTAs/SM)

// ---------------- device scratch (static; no allocation) ---------------------
__device__ __half g_xh[(size_t)NTOK * IN];
__device__ __half g_Mh[(size_t)NS * OUT * IN];
__device__ int g_counts[NS];          // zero at load; gemm re-zeros for next replay
__device__ int g_cursor[NS];
__device__ int g_perm[NTOK];
__device__ int g_tile_sys[MAXT];
__device__ int g_tile_start[MAXT];
__device__ int g_tile_rows[MAXT];

// ---------------- helpers -----------------------------------------------------
__device__ __forceinline__ uint32_t smem_u32(const void* p) {
    uint32_t a;
    asm("{ .reg .u64 t; cvta.to.shared.u64 t, %1; cvt.u32.u64 %0, t; }"
        : "=r"(a) : "l"(p));
    return a;
}
__device__ __forceinline__ void cpa16(uint32_t dst, const void* src) {
    asm volatile("cp.async.cg.shared.global [%0], [%1], 16;"
                 :: "r"(dst), "l"(src) : "memory");
}
__device__ __forceinline__ void ldsm4(uint32_t* r, uint32_t addr) {
    asm volatile("ldmatrix.sync.aligned.m8n8.x4.shared.b16 {%0,%1,%2,%3}, [%4];"
                 : "=r"(r[0]), "=r"(r[1]), "=r"(r[2]), "=r"(r[3]) : "r"(addr));
}
__device__ __forceinline__ void mma16816(float* c, const uint32_t* a,
                                         uint32_t b0, uint32_t b1) {
    asm volatile(
        "mma.sync.aligned.m16n8k16.row.col.f32.f16.f16.f32 "
        "{%0,%1,%2,%3}, {%4,%5,%6,%7}, {%8,%9}, {%0,%1,%2,%3};"
        : "+f"(c[0]), "+f"(c[1]), "+f"(c[2]), "+f"(c[3])
        : "r"(a[0]), "r"(a[1]), "r"(a[2]), "r"(a[3]), "r"(b0), "r"(b1));
}
__device__ __forceinline__ uint2 round4h(float4 v) {
    __half2 h01 = __floats2half2_rn(v.x, v.y);
    __half2 h23 = __floats2half2_rn(v.z, v.w);
    return make_uint2(*(uint32_t*)&h01, *(uint32_t*)&h23);
}

// ---------------- kernel 1: fused mix (blocks 0..255) + hist (blocks 256..511)
__global__ __launch_bounds__(256) void mixhist_kernel(const float* __restrict__ W,
                                                      const float* __restrict__ coeff,
                                                      const int* __restrict__ bi) {
    int bx = blockIdx.x;
    int tid = threadIdx.x;
    if (bx < 256) {
        __shared__ float sc[NS * NE];
        for (int i = tid; i < NS * NE; i += blockDim.x) sc[i] = coeff[i];
        __syncthreads();

        int idx = bx * 256 + tid;       // over OUT*IN/4
        int o  = idx >> 7;
        int q  = idx & 127;
        int i4 = q * 4;

        float4 w[NE];
#pragma unroll
        for (int e = 0; e < NE; ++e)
            w[e] = *(const float4*)(W + (size_t)e * OUT * IN + o * IN + i4);

#pragma unroll 4
        for (int s = 0; s < NS; ++s) {
            float4 acc = make_float4(0.f, 0.f, 0.f, 0.f);
#pragma unroll
            for (int e = 0; e < NE; ++e) {
                float c = sc[s * NE + e];
                acc.x = fmaf(c, w[e].x, acc.x);
                acc.y = fmaf(c, w[e].y, acc.y);
                acc.z = fmaf(c, w[e].z, acc.z);
                acc.w = fmaf(c, w[e].w, acc.w);
            }
            ((uint2*)(g_Mh + (size_t)(s * OUT + o) * IN))[q] = round4h(acc);
        }
    } else {
        __shared__ int h[NS];
        if (tid < NS) h[tid] = 0;
        __syncthreads();
        int n = (bx - 256) * 256 + tid;
        atomicAdd(&h[bi[n]], 1);
        __syncthreads();
        if (tid < NS && h[tid] != 0) atomicAdd(&g_counts[tid], h[tid]);
    }
}

// ---------------- kernel 2: scan + tile table ---------------------------------
__global__ void plan_kernel() {
    __shared__ int cnt[NS], offs[NS], tbase[NS];
    int tid = threadIdx.x;
    if (tid < NS) cnt[tid] = g_counts[tid];
    __syncthreads();
    if (tid == 0) {
        int off = 0, tb = 0;
        for (int s = 0; s < NS; ++s) {
            offs[s] = off; tbase[s] = tb;
            off += cnt[s];
            tb  += (cnt[s] + TM - 1) / TM;
        }
    }
    __syncthreads();
    for (int i = tid; i < MAXT; i += blockDim.x) g_tile_rows[i] = 0;
    __syncthreads();
    if (tid < NS) {
        int s = tid, c = cnt[s], nt = (c + TM - 1) / TM;
        int tb = tbase[s], off = offs[s];
        g_cursor[s] = off;
        for (int k = 0; k < nt; ++k) {
            g_tile_sys[tb + k]   = s;
            g_tile_start[tb + k] = off + k * TM;
            int rem = c - k * TM;
            g_tile_rows[tb + k]  = rem < TM ? rem : TM;
        }
    }
}

// ---------------- kernel 3: scatter + gather/convert x rows -------------------
__global__ __launch_bounds__(1024) void scatter_conv(const int* __restrict__ bi,
                                                     const float* __restrict__ x) {
    __shared__ int lc[NS], lbase[NS];
    __shared__ int spos[1024];
    int tid = threadIdx.x;
    if (tid < NS) lc[tid] = 0;
    __syncthreads();
    int n = blockIdx.x * 1024 + tid;
    int s = bi[n];
    int r = atomicAdd(&lc[s], 1);
    __syncthreads();
    if (tid < NS && lc[tid] > 0) lbase[tid] = atomicAdd(&g_cursor[tid], lc[tid]);
    __syncthreads();
    int pos = lbase[s] + r;
    g_perm[pos] = n;
    spos[tid] = pos;
    __syncthreads();

    int lane = tid & 31, w = tid >> 5;
    int tokbase = blockIdx.x * 1024 + w * 32;
#pragma unroll 1
    for (int t = 0; t < 32; ++t) {
        int tok = tokbase + t;
        int p   = spos[w * 32 + t];
        const float4* src = (const float4*)(x + (size_t)tok * IN);
        uint2* dst = (uint2*)(g_xh + (size_t)p * IN);
#pragma unroll
        for (int pass = 0; pass < 4; ++pass) {
            int q = pass * 32 + lane;
            dst[q] = round4h(src[q]);
        }
    }
}

// ---------------- kernel 4: grouped GEMM, fp16, 4 warps, 4 CTAs/SM ------------
// CTA: 128 tokens x 64 outputs; 4 warps (2x2), warp tile 64x32.
// K=512 in 8 chunks of 64; 2-stage cp.async pipeline; double-buffered fragments.
// grid = (8 col-groups, 576 tiles): col CTAs of one tile adjacent for L2 reuse.
__global__ __launch_bounds__(128, 4) void gemm_kernel(const float* __restrict__ bias,
                                                      float* __restrict__ out) {
    if (blockIdx.x == 0 && blockIdx.y == 0 && threadIdx.x < NS)
        g_counts[threadIdx.x] = 0;

    int bt = blockIdx.y;
    int rows = g_tile_rows[bt];
    if (rows == 0) return;
    int sys       = g_tile_sys[bt];
    int row_start = g_tile_start[bt];
    int col0      = blockIdx.x * TN;

    extern __shared__ __align__(16) char smem[];
    uint32_t sm = smem_u32(smem);
    int tid = threadIdx.x, lane = tid & 31, wid = tid >> 5;
    int wm = wid >> 1, wn = wid & 1;      // 2 x 2 warp grid

    int* sperm = (int*)(smem + OFF_PERM);
    if (tid < TM) {
        int rsi = row_start + tid;
        if (rsi > NTOK - 1) rsi = NTOK - 1;
        sperm[tid] = g_perm[rsi];
    }

    // loaders: 128 threads; A: 128 rows x 8 segs (8/thread); B: 64 rows (4/thread)
    int row16 = tid >> 3;     // 0..15
    int seg   = tid & 7;
    size_t sysbase = (size_t)sys * OUT * IN;

    auto load_chunk = [&](int stage, int k0) {
        uint32_t sb = sm + stage * STAGE_BYTES;
#pragma unroll
        for (int h = 0; h < 8; ++h) {
            int row = row16 + h * 16;
            int srcrow = row_start + row;
            if (srcrow > NTOK - 1) srcrow = NTOK - 1;
            cpa16(sb + row * LDSS + seg * 16,
                  g_xh + (size_t)srcrow * IN + k0 + seg * 8);
        }
#pragma unroll
        for (int h = 0; h < 4; ++h) {
            int row = row16 + h * 16;
            cpa16(sb + OFF_B + row * LDSS + seg * 16,
                  g_Mh + sysbase + (size_t)(col0 + row) * IN + k0 + seg * 8);
        }
        asm volatile("cp.async.commit_group;" ::: "memory");
    };

    float acc[4][4][4];
#pragma unroll
    for (int mf = 0; mf < 4; ++mf)
#pragma unroll
        for (int nf = 0; nf < 4; ++nf)
#pragma unroll
            for (int r = 0; r < 4; ++r) acc[mf][nf][r] = 0.f;

    load_chunk(0, 0);

    int lrow = lane & 15, kseg = lane >> 4;
    uint32_t a_base = (uint32_t)((wm * 64 + lrow) * LDSS + kseg * 16);
    uint32_t b_base = (uint32_t)(OFF_B + (wn * 32 + lrow) * LDSS + kseg * 16);

    uint32_t aa[2][4][4], bb[2][2][4];

#pragma unroll 1
    for (int c = 0; c < NCHUNK; ++c) {
        asm volatile("cp.async.wait_group 0;" ::: "memory");
        __syncthreads();
        // safe: stage (c+1)&1 was last READ during compute of c-1, which all
        // threads finished before reaching the barrier above.
        if (c + 1 < NCHUNK) load_chunk((c + 1) & 1, (c + 1) * KC);

        uint32_t sb = sm + (c & 1) * STAGE_BYTES;

        // prologue: fragments for kk=0
#pragma unroll
        for (int mf = 0; mf < 4; ++mf)
            ldsm4(aa[0][mf], sb + a_base + mf * 16 * LDSS);
#pragma unroll
        for (int bf = 0; bf < 2; ++bf)
            ldsm4(bb[0][bf], sb + b_base + bf * 16 * LDSS);

#pragma unroll
        for (int kk = 0; kk < 4; ++kk) {
            int cur = kk & 1;
            if (kk < 3) {
                int nxt = cur ^ 1;
#pragma unroll
                for (int mf = 0; mf < 4; ++mf)
                    ldsm4(aa[nxt][mf], sb + a_base + mf * 16 * LDSS + (kk + 1) * 32);
#pragma unroll
                for (int bf = 0; bf < 2; ++bf)
                    ldsm4(bb[nxt][bf], sb + b_base + bf * 16 * LDSS + (kk + 1) * 32);
            }
#pragma unroll
            for (int mf = 0; mf < 4; ++mf)
#pragma unroll
                for (int nf = 0; nf < 4; ++nf)
                    mma16816(acc[mf][nf], aa[cur][mf],
                             bb[cur][nf >> 1][nf & 1], bb[cur][nf >> 1][(nf & 1) + 2]);
        }
    }

    // ---------------- epilogue: bias + scatter -------------------------------
    int g  = lane >> 2;
    int tc = (lane & 3) * 2;
    const float* bptr = bias + col0 + wn * 32 + tc;
    float2 bv[4];
#pragma unroll
    for (int nf = 0; nf < 4; ++nf)
        bv[nf] = make_float2(bptr[nf * 8], bptr[nf * 8 + 1]);

#pragma unroll
    for (int mf = 0; mf < 4; ++mf) {
#pragma unroll
        for (int rh = 0; rh < 2; ++rh) {
            int lr = wm * 64 + mf * 16 + rh * 8 + g;
            if (lr < rows) {
                float* orow = out + (size_t)sperm[lr] * OUT + col0 + wn * 32 + tc;
#pragma unroll
                for (int nf = 0; nf < 4; ++nf) {
                    float2 v = make_float2(acc[mf][nf][rh * 2]     + bv[nf].x,
                                           acc[mf][nf][rh * 2 + 1] + bv[nf].y);
                    *(float2*)(orow + nf * 8) = v;
                }
            }
        }
    }
}

// ---------------- launch -----------------------------------------------------
extern "C" void kernel_launch(void* const* d_in, const int* in_sizes, int n_in,
                              void* d_out, int out_size) {
    const float* x     = (const float*)d_in[0];
    const float* coeff = (const float*)d_in[1];
    const int*   bidx  = (const int*)d_in[2];
    const float* W     = (const float*)d_in[3];
    const float* bias  = (const float*)d_in[4];
    float*       out   = (float*)d_out;

    cudaFuncSetAttribute(gemm_kernel, cudaFuncAttributeMaxDynamicSharedMemorySize,
                         GSMEM);

    mixhist_kernel<<<512, 256>>>(W, coeff, bidx);
    plan_kernel<<<1, 256>>>();
    scatter_conv<<<NTOK / 1024, 1024>>>(bidx, x);
    gemm_kernel<<<dim3(OUT / TN, MAXT), 128, GSMEM>>>(bias, out);
}

// round 10
// speedup vs baseline: 2.7976x; 1.0814x over previous
#include <cuda_runtime.h>
#include <cuda_fp16.h>
#include <cstdint>

// Problem constants
#define NTOK 65536
#define IN   512
#define OUT  512
#define NE   8
#define NS   64

// GEMM tiling
#define TM 128
#define TN 64
#define KC 64
#define NCHUNK (IN / KC)          // 8
#define MAXT 576
#define LDSS 144                  // 128B data + 16B pad: conflict-free ldmatrix

#define A_PLANE (TM * LDSS)       // 18432
#define B_PLANE (TN * LDSS)       // 9216
#define OFF_B   A_PLANE
#define STAGE_BYTES (A_PLANE + B_PLANE)       // 27648
#define OFF_PERM (2 * STAGE_BYTES)            // 55296
#define GSMEM (OFF_PERM + 512)                // 55808  (4 CTAs/SM)

// ---------------- device scratch (static; no allocation) ---------------------
__device__ __half g_xh[(size_t)NTOK * IN];
__device__ __half g_Mh[(size_t)NS * OUT * IN];
__device__ int g_counts[NS];          // zero at load; gemm re-zeros for next replay
__device__ int g_cursor[NS];
__device__ int g_perm[NTOK];
__device__ int g_tile_sys[MAXT];
__device__ int g_tile_start[MAXT];
__device__ int g_tile_rows[MAXT];

// ---------------- helpers -----------------------------------------------------
__device__ __forceinline__ uint32_t smem_u32(const void* p) {
    uint32_t a;
    asm("{ .reg .u64 t; cvta.to.shared.u64 t, %1; cvt.u32.u64 %0, t; }"
        : "=r"(a) : "l"(p));
    return a;
}
__device__ __forceinline__ void cpa16(uint32_t dst, const void* src) {
    asm volatile("cp.async.cg.shared.global [%0], [%1], 16;"
                 :: "r"(dst), "l"(src) : "memory");
}
__device__ __forceinline__ void ldsm4(uint32_t* r, uint32_t addr) {
    asm volatile("ldmatrix.sync.aligned.m8n8.x4.shared.b16 {%0,%1,%2,%3}, [%4];"
                 : "=r"(r[0]), "=r"(r[1]), "=r"(r[2]), "=r"(r[3]) : "r"(addr));
}
__device__ __forceinline__ void mma16816(float* c, const uint32_t* a,
                                         uint32_t b0, uint32_t b1) {
    asm volatile(
        "mma.sync.aligned.m16n8k16.row.col.f32.f16.f16.f32 "
        "{%0,%1,%2,%3}, {%4,%5,%6,%7}, {%8,%9}, {%0,%1,%2,%3};"
        : "+f"(c[0]), "+f"(c[1]), "+f"(c[2]), "+f"(c[3])
        : "r"(a[0]), "r"(a[1]), "r"(a[2]), "r"(a[3]), "r"(b0), "r"(b1));
}
__device__ __forceinline__ uint2 round4h(float4 v) {
    __half2 h01 = __floats2half2_rn(v.x, v.y);
    __half2 h23 = __floats2half2_rn(v.z, v.w);
    return make_uint2(*(uint32_t*)&h01, *(uint32_t*)&h23);
}

// ---------------- kernel 1: histogram (tiny, block-aggregated) ----------------
__global__ __launch_bounds__(1024) void hist_kernel(const int* __restrict__ bi) {
    __shared__ int h[NS];
    int tid = threadIdx.x;
    if (tid < NS) h[tid] = 0;
    __syncthreads();
    int n = blockIdx.x * 1024 + tid;
    atomicAdd(&h[bi[n]], 1);
    __syncthreads();
    if (tid < NS && h[tid] != 0) atomicAdd(&g_counts[tid], h[tid]);
}

// ---------------- kernel 2: scan + tile table ---------------------------------
__global__ void plan_kernel() {
    __shared__ int cnt[NS], offs[NS], tbase[NS];
    int tid = threadIdx.x;
    if (tid < NS) cnt[tid] = g_counts[tid];
    __syncthreads();
    if (tid == 0) {
        int off = 0, tb = 0;
        for (int s = 0; s < NS; ++s) {
            offs[s] = off; tbase[s] = tb;
            off += cnt[s];
            tb  += (cnt[s] + TM - 1) / TM;
        }
    }
    __syncthreads();
    for (int i = tid; i < MAXT; i += blockDim.x) g_tile_rows[i] = 0;
    __syncthreads();
    if (tid < NS) {
        int s = tid, c = cnt[s], nt = (c + TM - 1) / TM;
        int tb = tbase[s], off = offs[s];
        g_cursor[s] = off;
        for (int k = 0; k < nt; ++k) {
            g_tile_sys[tb + k]   = s;
            g_tile_start[tb + k] = off + k * TM;
            int rem = c - k * TM;
            g_tile_rows[tb + k]  = rem < TM ? rem : TM;
        }
    }
}

// ---------------- kernel 3: scatter+convert (blocks 0..63) | mix (64..127) ----
// Mix (12us) hides under the bandwidth-bound scatter/convert (35us).
__global__ __launch_bounds__(1024) void scattermix_kernel(const int* __restrict__ bi,
                                                          const float* __restrict__ x,
                                                          const float* __restrict__ W,
                                                          const float* __restrict__ coeff) {
    int bx = blockIdx.x;
    int tid = threadIdx.x;
    if (bx < 64) {
        // ---- scatter + gather/convert token rows ----
        __shared__ int lc[NS], lbase[NS];
        __shared__ int spos[1024];
        if (tid < NS) lc[tid] = 0;
        __syncthreads();
        int n = bx * 1024 + tid;
        int s = bi[n];
        int r = atomicAdd(&lc[s], 1);
        __syncthreads();
        if (tid < NS && lc[tid] > 0) lbase[tid] = atomicAdd(&g_cursor[tid], lc[tid]);
        __syncthreads();
        int pos = lbase[s] + r;
        g_perm[pos] = n;
        spos[tid] = pos;
        __syncthreads();

        int lane = tid & 31, w = tid >> 5;
        int tokbase = bx * 1024 + w * 32;
#pragma unroll 1
        for (int t = 0; t < 32; ++t) {
            int tok = tokbase + t;
            int p   = spos[w * 32 + t];
            const float4* src = (const float4*)(x + (size_t)tok * IN);
            uint2* dst = (uint2*)(g_xh + (size_t)p * IN);
#pragma unroll
            for (int pass = 0; pass < 4; ++pass) {
                int q = pass * 32 + lane;
                dst[q] = round4h(src[q]);
            }
        }
    } else {
        // ---- mix: M[s] = sum_e c[s,e] * W[e], rounded fp16 ----
        __shared__ float sc[NS * NE];
        for (int i = tid; i < NS * NE; i += 1024) sc[i] = coeff[i];
        __syncthreads();

        int idx = (bx - 64) * 1024 + tid;   // over OUT*IN/4 = 65536
        int o  = idx >> 7;
        int q  = idx & 127;
        int i4 = q * 4;

        float4 w[NE];
#pragma unroll
        for (int e = 0; e < NE; ++e)
            w[e] = *(const float4*)(W + (size_t)e * OUT * IN + o * IN + i4);

#pragma unroll 4
        for (int s = 0; s < NS; ++s) {
            float4 acc = make_float4(0.f, 0.f, 0.f, 0.f);
#pragma unroll
            for (int e = 0; e < NE; ++e) {
                float c = sc[s * NE + e];
                acc.x = fmaf(c, w[e].x, acc.x);
                acc.y = fmaf(c, w[e].y, acc.y);
                acc.z = fmaf(c, w[e].z, acc.z);
                acc.w = fmaf(c, w[e].w, acc.w);
            }
            ((uint2*)(g_Mh + (size_t)(s * OUT + o) * IN))[q] = round4h(acc);
        }
    }
}

// ---------------- kernel 4: grouped GEMM, fp16, 4 warps, 4 CTAs/SM ------------
// CTA: 128 tokens x 64 outputs; 4 warps (2x2), warp tile 64x32.
// K=512, 8 chunks of 64, FULLY UNROLLED; all gmem pointers hoisted (chunk
// advance = compile-time immediate in LDGSTS); 2-stage cp.async pipeline.
__global__ __launch_bounds__(128, 4) void gemm_kernel(const float* __restrict__ bias,
                                                      float* __restrict__ out) {
    if (blockIdx.x == 0 && blockIdx.y == 0 && threadIdx.x < NS)
        g_counts[threadIdx.x] = 0;

    int bt = blockIdx.y;
    int rows = g_tile_rows[bt];
    if (rows == 0) return;
    int sys       = g_tile_sys[bt];
    int row_start = g_tile_start[bt];
    int col0      = blockIdx.x * TN;

    extern __shared__ __align__(16) char smem[];
    uint32_t sm = smem_u32(smem);
    int tid = threadIdx.x, lane = tid & 31, wid = tid >> 5;
    int wm = wid >> 1, wn = wid & 1;      // 2 x 2 warp grid

    int* sperm = (int*)(smem + OFF_PERM);
    if (tid < TM) {
        int rsi = row_start + tid;
        if (rsi > NTOK - 1) rsi = NTOK - 1;
        sperm[tid] = g_perm[rsi];
    }

    // ---- hoisted loader pointers (computed ONCE) ----
    int row16 = tid >> 3;     // 0..15
    int seg   = tid & 7;
    const __half* apt[8];
#pragma unroll
    for (int h = 0; h < 8; ++h) {
        int srcrow = row_start + row16 + h * 16;
        if (srcrow > NTOK - 1) srcrow = NTOK - 1;
        apt[h] = g_xh + (size_t)srcrow * IN + seg * 8;
    }
    const __half* bpt = g_Mh + (size_t)sys * OUT * IN
                      + (size_t)(col0 + row16) * IN + seg * 8;
    uint32_t dstA = sm + row16 * LDSS + seg * 16;

    // load chunk c into stage: all offsets compile-time when c is constant
    auto load_chunk = [&](uint32_t stoff, int c) {
#pragma unroll
        for (int h = 0; h < 8; ++h)
            cpa16(stoff + dstA + h * 16 * LDSS, apt[h] + c * KC);
#pragma unroll
        for (int h = 0; h < 4; ++h)
            cpa16(stoff + dstA + OFF_B + h * 16 * LDSS, bpt + (size_t)h * 16 * IN + c * KC);
        asm volatile("cp.async.commit_group;" ::: "memory");
    };

    float acc[4][4][4];
#pragma unroll
    for (int mf = 0; mf < 4; ++mf)
#pragma unroll
        for (int nf = 0; nf < 4; ++nf)
#pragma unroll
            for (int r = 0; r < 4; ++r) acc[mf][nf][r] = 0.f;

    load_chunk(0, 0);

    int lrow = lane & 15, kseg = lane >> 4;
    uint32_t a_base = sm + (uint32_t)((wm * 64 + lrow) * LDSS + kseg * 16);
    uint32_t b_base = sm + (uint32_t)(OFF_B + (wn * 32 + lrow) * LDSS + kseg * 16);

    uint32_t aa[2][4][4], bb[2][2][4];

#pragma unroll
    for (int c = 0; c < NCHUNK; ++c) {
        asm volatile("cp.async.wait_group 0;" ::: "memory");
        __syncthreads();
        if (c + 1 < NCHUNK) load_chunk(((c + 1) & 1) * STAGE_BYTES, c + 1);

        uint32_t so = (uint32_t)((c & 1) * STAGE_BYTES);

#pragma unroll
        for (int mf = 0; mf < 4; ++mf)
            ldsm4(aa[0][mf], a_base + so + mf * 16 * LDSS);
#pragma unroll
        for (int bf = 0; bf < 2; ++bf)
            ldsm4(bb[0][bf], b_base + so + bf * 16 * LDSS);

#pragma unroll
        for (int kk = 0; kk < 4; ++kk) {
            int cur = kk & 1;
            if (kk < 3) {
                int nxt = cur ^ 1;
#pragma unroll
                for (int mf = 0; mf < 4; ++mf)
                    ldsm4(aa[nxt][mf], a_base + so + mf * 16 * LDSS + (kk + 1) * 32);
#pragma unroll
                for (int bf = 0; bf < 2; ++bf)
                    ldsm4(bb[nxt][bf], b_base + so + bf * 16 * LDSS + (kk + 1) * 32);
            }
#pragma unroll
            for (int mf = 0; mf < 4; ++mf)
#pragma unroll
                for (int nf = 0; nf < 4; ++nf)
                    mma16816(acc[mf][nf], aa[cur][mf],
                             bb[cur][nf >> 1][nf & 1], bb[cur][nf >> 1][(nf & 1) + 2]);
        }
    }

    // ---------------- epilogue: bias + scatter -------------------------------
    int g  = lane >> 2;
    int tc = (lane & 3) * 2;
    const float* bptr = bias + col0 + wn * 32 + tc;
    float2 bv[4];
#pragma unroll
    for (int nf = 0; nf < 4; ++nf)
        bv[nf] = make_float2(bptr[nf * 8], bptr[nf * 8 + 1]);

#pragma unroll
    for (int mf = 0; mf < 4; ++mf) {
#pragma unroll
        for (int rh = 0; rh < 2; ++rh) {
            int lr = wm * 64 + mf * 16 + rh * 8 + g;
            if (lr < rows) {
                float* orow = out + (size_t)sperm[lr] * OUT + col0 + wn * 32 + tc;
#pragma unroll
                for (int nf = 0; nf < 4; ++nf) {
                    float2 v = make_float2(acc[mf][nf][rh * 2]     + bv[nf].x,
                                           acc[mf][nf][rh * 2 + 1] + bv[nf].y);
                    *(float2*)(orow + nf * 8) = v;
                }
            }
        }
    }
}

// ---------------- launch -----------------------------------------------------
extern "C" void kernel_launch(void* const* d_in, const int* in_sizes, int n_in,
                              void* d_out, int out_size) {
    const float* x     = (const float*)d_in[0];
    const float* coeff = (const float*)d_in[1];
    const int*   bidx  = (const int*)d_in[2];
    const float* W     = (const float*)d_in[3];
    const float* bias  = (const float*)d_in[4];
    float*       out   = (float*)d_out;

    cudaFuncSetAttribute(gemm_kernel, cudaFuncAttributeMaxDynamicSharedMemorySize,
                         GSMEM);

    hist_kernel<<<NTOK / 1024, 1024>>>(bidx);
    plan_kernel<<<1, 256>>>();
    scattermix_kernel<<<128, 1024>>>(bidx, x, W, coeff);
    gemm_kernel<<<dim3(OUT / TN, MAXT), 128, GSMEM>>>(bias, out);
}

// round 11
// speedup vs baseline: 2.9719x; 1.0623x over previous
#include <cuda_runtime.h>
#include <cuda_fp16.h>
#include <cstdint>

// Problem constants
#define NTOK 65536
#define IN   512
#define OUT  512
#define NE   8
#define NS   64

// GEMM tiling
#define TM 128
#define TN 64
#define KC 64
#define NCHUNK (IN / KC)          // 8
#define MAXT 576
#define LDSS 144                  // 128B data + 16B pad: conflict-free ldmatrix

#define A_PLANE (TM * LDSS)       // 18432
#define B_PLANE (TN * LDSS)       // 9216
#define OFF_B   A_PLANE
#define STAGE_BYTES (A_PLANE + B_PLANE)       // 27648
#define OFF_PERM (2 * STAGE_BYTES)            // 55296
#define GSMEM (OFF_PERM + 512)                // 55808  (4 CTAs/SM)

// ---------------- device scratch (static; no allocation) ---------------------
__device__ __half g_xh[(size_t)NTOK * IN];    // fp16(x), ORIGINAL token order
__device__ __half g_Mh[(size_t)NS * OUT * IN];
__device__ int g_counts[NS];          // zeroed by plan block after use
__device__ int g_cursor[NS];
__device__ int g_perm[NTOK];
__device__ int g_tile_sys[MAXT];
__device__ int g_tile_start[MAXT];
__device__ int g_tile_rows[MAXT];
__device__ int g_hist_done;           // reset by plan block
__device__ int g_plan_flag;           // reset by gemm block (0,0)

// ---------------- helpers -----------------------------------------------------
__device__ __forceinline__ uint32_t smem_u32(const void* p) {
    uint32_t a;
    asm("{ .reg .u64 t; cvta.to.shared.u64 t, %1; cvt.u32.u64 %0, t; }"
        : "=r"(a) : "l"(p));
    return a;
}
__device__ __forceinline__ void cpa16(uint32_t dst, const void* src) {
    asm volatile("cp.async.cg.shared.global [%0], [%1], 16;"
                 :: "r"(dst), "l"(src) : "memory");
}
__device__ __forceinline__ void ldsm4(uint32_t* r, uint32_t addr) {
    asm volatile("ldmatrix.sync.aligned.m8n8.x4.shared.b16 {%0,%1,%2,%3}, [%4];"
                 : "=r"(r[0]), "=r"(r[1]), "=r"(r[2]), "=r"(r[3]) : "r"(addr));
}
__device__ __forceinline__ void mma16816(float* c, const uint32_t* a,
                                         uint32_t b0, uint32_t b1) {
    asm volatile(
        "mma.sync.aligned.m16n8k16.row.col.f32.f16.f16.f32 "
        "{%0,%1,%2,%3}, {%4,%5,%6,%7}, {%8,%9}, {%0,%1,%2,%3};"
        : "+f"(c[0]), "+f"(c[1]), "+f"(c[2]), "+f"(c[3])
        : "r"(a[0]), "r"(a[1]), "r"(a[2]), "r"(a[3]), "r"(b0), "r"(b1));
}
__device__ __forceinline__ uint2 round4h(float4 v) {
    __half2 h01 = __floats2half2_rn(v.x, v.y);
    __half2 h23 = __floats2half2_rn(v.z, v.w);
    return make_uint2(*(uint32_t*)&h01, *(uint32_t*)&h23);
}

// ---------------- kernel 1: fused prep ---------------------------------------
// blocks 0..63:    hist (last-done block runs plan inline, sets g_plan_flag)
// blocks 64..127:  scatter (local phase immediately; spins on flag for bases)
// blocks 128..383: convert x -> fp16 (independent)
// blocks 384..511: mix weights -> fp16 (independent)
// All 512 blocks resident (256 threads, low regs) => spin is safe.
__global__ __launch_bounds__(256) void prep_kernel(const int* __restrict__ bi,
                                                   const float* __restrict__ x,
                                                   const float* __restrict__ W,
                                                   const float* __restrict__ coeff) {
    int bx = blockIdx.x;
    int tid = threadIdx.x;

    if (bx < 64) {
        // ---- histogram over tokens [bx*1024, +1024) ----
        __shared__ int h[NS];
        __shared__ int lastdone;
        if (tid < NS) h[tid] = 0;
        __syncthreads();
        int base = bx * 1024;
#pragma unroll
        for (int j = 0; j < 4; ++j)
            atomicAdd(&h[bi[base + j * 256 + tid]], 1);
        __syncthreads();
        if (tid < NS && h[tid] != 0) atomicAdd(&g_counts[tid], h[tid]);
        __threadfence();
        __syncthreads();
        if (tid == 0) lastdone = atomicAdd(&g_hist_done, 1);
        __syncthreads();
        if (lastdone != 63) return;

        // ---- plan (runs in the last-finishing hist block) ----
        __threadfence();
        __shared__ int cnt[NS], offs[NS], tbase[NS];
        if (tid < NS) cnt[tid] = g_counts[tid];
        __syncthreads();
        if (tid == 0) {
            int off = 0, tb = 0;
            for (int s = 0; s < NS; ++s) {
                offs[s] = off; tbase[s] = tb;
                off += cnt[s];
                tb  += (cnt[s] + TM - 1) / TM;
            }
        }
        __syncthreads();
        for (int i = tid; i < MAXT; i += 256) g_tile_rows[i] = 0;
        __syncthreads();
        if (tid < NS) {
            int s = tid, c = cnt[s], nt = (c + TM - 1) / TM;
            int tb = tbase[s], off = offs[s];
            g_cursor[s] = off;
            for (int k = 0; k < nt; ++k) {
                g_tile_sys[tb + k]   = s;
                g_tile_start[tb + k] = off + k * TM;
                int rem = c - k * TM;
                g_tile_rows[tb + k]  = rem < TM ? rem : TM;
            }
            g_counts[s] = 0;           // reset for next graph replay
        }
        if (tid == 0) g_hist_done = 0; // reset for next graph replay
        __threadfence();
        __syncthreads();
        if (tid == 0) atomicExch(&g_plan_flag, 1);   // release
    } else if (bx < 128) {
        // ---- scatter tokens [(bx-64)*1024, +1024): write g_perm ----
        __shared__ int lc[NS], lbase[NS];
        if (tid < NS) lc[tid] = 0;
        __syncthreads();
        int base = (bx - 64) * 1024;
        int myn[4], mys[4], myr[4];
#pragma unroll
        for (int j = 0; j < 4; ++j) {
            int n = base + j * 256 + tid;
            int s = bi[n];
            myn[j] = n; mys[j] = s;
            myr[j] = atomicAdd(&lc[s], 1);
        }
        __syncthreads();
        // wait for plan to publish g_cursor
        if (tid == 0) {
            while (atomicAdd(&g_plan_flag, 0) == 0) __nanosleep(200);
        }
        __syncthreads();
        __threadfence();               // acquire
        if (tid < NS && lc[tid] > 0) lbase[tid] = atomicAdd(&g_cursor[tid], lc[tid]);
        __syncthreads();
#pragma unroll
        for (int j = 0; j < 4; ++j)
            g_perm[lbase[mys[j]] + myr[j]] = myn[j];
    } else if (bx < 384) {
        // ---- convert x -> fp16, original order; contiguous streaming ----
        const float4* xin = (const float4*)x;
        uint2* xo = (uint2*)g_xh;
        int b0 = (bx - 128) * 32768 + tid;   // 32768 float4 per block
#pragma unroll 8
        for (int i = 0; i < 128; ++i) {
            int gidx = b0 + i * 256;
            xo[gidx] = round4h(xin[gidx]);
        }
    } else {
        // ---- mix: M[s] = sum_e c[s,e] * W[e], rounded fp16 ----
        __shared__ float sc[NS * NE];
        for (int i = tid; i < NS * NE; i += 256) sc[i] = coeff[i];
        __syncthreads();
#pragma unroll
        for (int half = 0; half < 2; ++half) {
            int idx = (bx - 384) * 512 + half * 256 + tid;  // over OUT*IN/4
            int o  = idx >> 7;
            int q  = idx & 127;
            int i4 = q * 4;
            float4 w[NE];
#pragma unroll
            for (int e = 0; e < NE; ++e)
                w[e] = *(const float4*)(W + (size_t)e * OUT * IN + o * IN + i4);
#pragma unroll 4
            for (int s = 0; s < NS; ++s) {
                float4 acc = make_float4(0.f, 0.f, 0.f, 0.f);
#pragma unroll
                for (int e = 0; e < NE; ++e) {
                    float c = sc[s * NE + e];
                    acc.x = fmaf(c, w[e].x, acc.x);
                    acc.y = fmaf(c, w[e].y, acc.y);
                    acc.z = fmaf(c, w[e].z, acc.z);
                    acc.w = fmaf(c, w[e].w, acc.w);
                }
                ((uint2*)(g_Mh + (size_t)(s * OUT + o) * IN))[q] = round4h(acc);
            }
        }
    }
}

// ---------------- kernel 2: grouped GEMM, fp16, 4 warps, 4 CTAs/SM ------------
// CTA: 128 tokens x 64 outputs; 4 warps (2x2), warp tile 64x32.
// A rows gathered via g_perm (x stored unpermuted); chunk advance = immediates.
__global__ __launch_bounds__(128, 4) void gemm_kernel(const float* __restrict__ bias,
                                                      float* __restrict__ out) {
    if (blockIdx.x == 0 && blockIdx.y == 0 && threadIdx.x == 0)
        g_plan_flag = 0;               // reset for next graph replay

    int bt = blockIdx.y;
    int rows = g_tile_rows[bt];
    if (rows == 0) return;
    int sys       = g_tile_sys[bt];
    int row_start = g_tile_start[bt];
    int col0      = blockIdx.x * TN;

    extern __shared__ __align__(16) char smem[];
    uint32_t sm = smem_u32(smem);
    int tid = threadIdx.x, lane = tid & 31, wid = tid >> 5;
    int wm = wid >> 1, wn = wid & 1;      // 2 x 2 warp grid

    int* sperm = (int*)(smem + OFF_PERM);
    if (tid < TM) {
        int rsi = row_start + tid;
        if (rsi > NTOK - 1) rsi = NTOK - 1;
        sperm[tid] = g_perm[rsi];
    }

    // ---- hoisted loader pointers (computed ONCE; perm-gathered A rows) ----
    int row16 = tid >> 3;     // 0..15
    int seg   = tid & 7;
    const __half* apt[8];
#pragma unroll
    for (int h = 0; h < 8; ++h) {
        int rsi = row_start + row16 + h * 16;
        if (rsi > NTOK - 1) rsi = NTOK - 1;
        int tok = __ldg(&g_perm[rsi]);
        apt[h] = g_xh + (size_t)tok * IN + seg * 8;
    }
    const __half* bpt = g_Mh + (size_t)sys * OUT * IN
                      + (size_t)(col0 + row16) * IN + seg * 8;
    uint32_t dstA = sm + row16 * LDSS + seg * 16;

    auto load_chunk = [&](uint32_t stoff, int c) {
#pragma unroll
        for (int h = 0; h < 8; ++h)
            cpa16(stoff + dstA + h * 16 * LDSS, apt[h] + c * KC);
#pragma unroll
        for (int h = 0; h < 4; ++h)
            cpa16(stoff + dstA + OFF_B + h * 16 * LDSS, bpt + (size_t)h * 16 * IN + c * KC);
        asm volatile("cp.async.commit_group;" ::: "memory");
    };

    float acc[4][4][4];
#pragma unroll
    for (int mf = 0; mf < 4; ++mf)
#pragma unroll
        for (int nf = 0; nf < 4; ++nf)
#pragma unroll
            for (int r = 0; r < 4; ++r) acc[mf][nf][r] = 0.f;

    load_chunk(0, 0);

    int lrow = lane & 15, kseg = lane >> 4;
    uint32_t a_base = sm + (uint32_t)((wm * 64 + lrow) * LDSS + kseg * 16);
    uint32_t b_base = sm + (uint32_t)(OFF_B + (wn * 32 + lrow) * LDSS + kseg * 16);

    uint32_t aa[2][4][4], bb[2][2][4];

#pragma unroll
    for (int c = 0; c < NCHUNK; ++c) {
        asm volatile("cp.async.wait_group 0;" ::: "memory");
        __syncthreads();
        if (c + 1 < NCHUNK) load_chunk(((c + 1) & 1) * STAGE_BYTES, c + 1);

        uint32_t so = (uint32_t)((c & 1) * STAGE_BYTES);

#pragma unroll
        for (int mf = 0; mf < 4; ++mf)
            ldsm4(aa[0][mf], a_base + so + mf * 16 * LDSS);
#pragma unroll
        for (int bf = 0; bf < 2; ++bf)
            ldsm4(bb[0][bf], b_base + so + bf * 16 * LDSS);

#pragma unroll
        for (int kk = 0; kk < 4; ++kk) {
            int cur = kk & 1;
            if (kk < 3) {
                int nxt = cur ^ 1;
#pragma unroll
                for (int mf = 0; mf < 4; ++mf)
                    ldsm4(aa[nxt][mf], a_base + so + mf * 16 * LDSS + (kk + 1) * 32);
#pragma unroll
                for (int bf = 0; bf < 2; ++bf)
                    ldsm4(bb[nxt][bf], b_base + so + bf * 16 * LDSS + (kk + 1) * 32);
            }
#pragma unroll
            for (int mf = 0; mf < 4; ++mf)
#pragma unroll
                for (int nf = 0; nf < 4; ++nf)
                    mma16816(acc[mf][nf], aa[cur][mf],
                             bb[cur][nf >> 1][nf & 1], bb[cur][nf >> 1][(nf & 1) + 2]);
        }
    }

    // ---------------- epilogue: bias + scatter -------------------------------
    int g  = lane >> 2;
    int tc = (lane & 3) * 2;
    const float* bptr = bias + col0 + wn * 32 + tc;
    float2 bv[4];
#pragma unroll
    for (int nf = 0; nf < 4; ++nf)
        bv[nf] = make_float2(bptr[nf * 8], bptr[nf * 8 + 1]);

#pragma unroll
    for (int mf = 0; mf < 4; ++mf) {
#pragma unroll
        for (int rh = 0; rh < 2; ++rh) {
            int lr = wm * 64 + mf * 16 + rh * 8 + g;
            if (lr < rows) {
                float* orow = out + (size_t)sperm[lr] * OUT + col0 + wn * 32 + tc;
#pragma unroll
                for (int nf = 0; nf < 4; ++nf) {
                    float2 v = make_float2(acc[mf][nf][rh * 2]     + bv[nf].x,
                                           acc[mf][nf][rh * 2 + 1] + bv[nf].y);
                    *(float2*)(orow + nf * 8) = v;
                }
            }
        }
    }
}

// ---------------- launch -----------------------------------------------------
extern "C" void kernel_launch(void* const* d_in, const int* in_sizes, int n_in,
                              void* d_out, int out_size) {
    const float* x     = (const float*)d_in[0];
    const float* coeff = (const float*)d_in[1];
    const int*   bidx  = (const int*)d_in[2];
    const float* W     = (const float*)d_in[3];
    const float* bias  = (const float*)d_in[4];
    float*       out   = (float*)d_out;

    cudaFuncSetAttribute(gemm_kernel, cudaFuncAttributeMaxDynamicSharedMemorySize,
                         GSMEM);

    prep_kernel<<<512, 256>>>(bidx, x, W, coeff);
    gemm_kernel<<<dim3(OUT / TN, MAXT), 128, GSMEM>>>(bias, out);
}